// round 11
// baseline (speedup 1.0000x reference)
#include <cuda_runtime.h>
#include <cuda_bf16.h>
#include <math.h>
#include <float.h>
#include <stdint.h>

#define S_LEN  2048
#define HID    4096
#define NH     32
#define HD     128
#define QKV_W  12288
#define Q_SIZE 4096
#define KV_SIZE 1024
#define BQ 64
#define BK 64

// GEMM tile config: CTA 128x128, K chunk 32 (bf16), 2 stages
#define CHK 32
#define STAGE 32768
#define AH_OFF 0
#define AL_OFF 8192
#define BH_OFF 16384
#define BL_OFF 24576
#define GEMM_SMEM (2 * STAGE)

// ---------------------------------------------------------------------------
// Scratch (device globals: allocation-free rule)
// ---------------------------------------------------------------------------
__device__ __align__(256) float g_qkv[(size_t)S_LEN * QKV_W];
__device__ __align__(256) __nv_bfloat16 g_hs_h[(size_t)S_LEN * HID];
__device__ __align__(256) __nv_bfloat16 g_hs_l[(size_t)S_LEN * HID];
__device__ __align__(256) __nv_bfloat16 g_wqkv_h[(size_t)QKV_W * HID];
__device__ __align__(256) __nv_bfloat16 g_wqkv_l[(size_t)QKV_W * HID];
__device__ __align__(256) __nv_bfloat16 g_wo_h[(size_t)HID * HID];
__device__ __align__(256) __nv_bfloat16 g_wo_l[(size_t)HID * HID];
__device__ __align__(256) __nv_bfloat16 g_at_h[(size_t)S_LEN * Q_SIZE];
__device__ __align__(256) __nv_bfloat16 g_at_l[(size_t)S_LEN * Q_SIZE];

// ---------------------------------------------------------------------------
// PTX helpers (plain sm_80-era PTX)
// ---------------------------------------------------------------------------
__device__ __forceinline__ uint32_t smem_u32(const void* p) {
    uint32_t a;
    asm("{ .reg .u64 t; cvta.to.shared.u64 t, %1; cvt.u32.u64 %0, t; }"
        : "=r"(a) : "l"(p));
    return a;
}
__device__ __forceinline__ void cpasync16(uint32_t dst, const void* src) {
    asm volatile("cp.async.cg.shared.global [%0], [%1], 16;"
                 :: "r"(dst), "l"(src) : "memory");
}
__device__ __forceinline__ void ldsm4(uint32_t* r, uint32_t addr) {
    asm volatile("ldmatrix.sync.aligned.m8n8.x4.shared.b16 {%0,%1,%2,%3}, [%4];"
                 : "=r"(r[0]), "=r"(r[1]), "=r"(r[2]), "=r"(r[3]) : "r"(addr));
}
__device__ __forceinline__ void mma_bf16(float* d, const uint32_t* a,
                                         const uint32_t* b) {
    asm volatile(
        "mma.sync.aligned.m16n8k16.row.col.f32.bf16.bf16.f32 "
        "{%0,%1,%2,%3}, {%4,%5,%6,%7}, {%8,%9}, {%0,%1,%2,%3};"
        : "+f"(d[0]), "+f"(d[1]), "+f"(d[2]), "+f"(d[3])
        : "r"(a[0]), "r"(a[1]), "r"(a[2]), "r"(a[3]), "r"(b[0]), "r"(b[1]));
}
__device__ __forceinline__ uint32_t swz(int row, int seg) {
    return row * 64 + ((seg ^ ((row >> 1) & 3)) << 4);
}
__device__ __forceinline__ void split2(float v0, float v1,
                                       uint32_t& hp, uint32_t& lp) {
    uint32_t u0 = __float_as_uint(v0) & 0xFFFF0000u;
    uint32_t u1 = __float_as_uint(v1) & 0xFFFF0000u;
    hp = (u0 >> 16) | u1;
    float r0 = v0 - __uint_as_float(u0);
    float r1 = v1 - __uint_as_float(u1);
    asm("cvt.rn.bf16x2.f32 %0, %1, %2;" : "=r"(lp) : "f"(r1), "f"(r0));
}

// ---------------------------------------------------------------------------
// fp32 -> bf16 hi/lo split
// ---------------------------------------------------------------------------
__global__ __launch_bounds__(256) void split_kernel(
    const float* __restrict__ x, __nv_bfloat16* __restrict__ hi,
    __nv_bfloat16* __restrict__ lo, int n)
{
    int i = (blockIdx.x * 256 + threadIdx.x) * 4;
    if (i >= n) return;
    float4 v = *(const float4*)(x + i);
    uint32_t h01, l01, h23, l23;
    split2(v.x, v.y, h01, l01);
    split2(v.z, v.w, h23, l23);
    *(uint2*)(hi + i) = make_uint2(h01, h23);
    *(uint2*)(lo + i) = make_uint2(l01, l23);
}

// ---------------------------------------------------------------------------
// HMMA split-bf16 GEMM NT (exact R3 version — proven 70% tensor)
// ---------------------------------------------------------------------------
__global__ __launch_bounds__(256, 2) void gemm_mma(
    const __nv_bfloat16* __restrict__ Ah, const __nv_bfloat16* __restrict__ Al,
    const __nv_bfloat16* __restrict__ Bh, const __nv_bfloat16* __restrict__ Bl,
    float* __restrict__ C, int M, int N, int K)
{
    extern __shared__ __align__(128) char smem_g[];
    const uint32_t sb = smem_u32(smem_g);
    const int tid  = threadIdx.x;
    const int lane = tid & 31, warp = tid >> 5;
    const int wm = warp >> 1, wn = warp & 1;
    const int m0 = blockIdx.y << 7, n0 = blockIdx.x << 7;
    const int NC = K / CHK;

    const int a_row = lane & 15;
    const int a_kh  = lane >> 4;
    const int b_row = (lane & 7) + ((lane & 16) >> 1);
    const int b_kh  = (lane >> 3) & 1;

    float acc[2][8][4];
#pragma unroll
    for (int mt = 0; mt < 2; mt++)
#pragma unroll
        for (int ng = 0; ng < 8; ng++)
#pragma unroll
            for (int r = 0; r < 4; r++) acc[mt][ng][r] = 0.f;

    auto load_chunk = [&](int c, int s) {
        const uint32_t st = sb + s * STAGE;
        const int k0 = c * CHK;
#pragma unroll
        for (int i = 0; i < 2; i++) {
            int idx = tid + i * 256;
            int row = idx >> 2, seg = idx & 3;
            uint32_t so = swz(row, seg);
            size_t ga = (size_t)(m0 + row) * K + k0 + seg * 8;
            size_t gb = (size_t)(n0 + row) * K + k0 + seg * 8;
            cpasync16(st + AH_OFF + so, Ah + ga);
            cpasync16(st + AL_OFF + so, Al + ga);
            cpasync16(st + BH_OFF + so, Bh + gb);
            cpasync16(st + BL_OFF + so, Bl + gb);
        }
        asm volatile("cp.async.commit_group;" ::: "memory");
    };

    load_chunk(0, 0);
    if (NC > 1) load_chunk(1, 1);

    for (int c = 0; c < NC; c++) {
        if (c + 1 < NC)
            asm volatile("cp.async.wait_group 1;" ::: "memory");
        else
            asm volatile("cp.async.wait_group 0;" ::: "memory");
        __syncthreads();

        const uint32_t st = sb + (c & 1) * STAGE;
#pragma unroll
        for (int kk = 0; kk < 2; kk++) {
            uint32_t ah[2][4], al[2][4], bh[4][4], bl[4][4];
#pragma unroll
            for (int mt = 0; mt < 2; mt++) {
                int r = wm * 32 + mt * 16 + a_row;
                ldsm4(ah[mt], st + AH_OFF + swz(r, kk * 2 + a_kh));
            }
#pragma unroll
            for (int g = 0; g < 4; g++) {
                int r = wn * 64 + g * 16 + b_row;
                ldsm4(bh[g], st + BH_OFF + swz(r, kk * 2 + b_kh));
            }
#pragma unroll
            for (int mt = 0; mt < 2; mt++)
#pragma unroll
                for (int ng = 0; ng < 8; ng++)
                    mma_bf16(acc[mt][ng], ah[mt], &bh[ng >> 1][(ng & 1) * 2]);
#pragma unroll
            for (int g = 0; g < 4; g++) {
                int r = wn * 64 + g * 16 + b_row;
                ldsm4(bl[g], st + BL_OFF + swz(r, kk * 2 + b_kh));
            }
#pragma unroll
            for (int mt = 0; mt < 2; mt++)
#pragma unroll
                for (int ng = 0; ng < 8; ng++)
                    mma_bf16(acc[mt][ng], ah[mt], &bl[ng >> 1][(ng & 1) * 2]);
#pragma unroll
            for (int mt = 0; mt < 2; mt++) {
                int r = wm * 32 + mt * 16 + a_row;
                ldsm4(al[mt], st + AL_OFF + swz(r, kk * 2 + a_kh));
            }
#pragma unroll
            for (int mt = 0; mt < 2; mt++)
#pragma unroll
                for (int ng = 0; ng < 8; ng++)
                    mma_bf16(acc[mt][ng], al[mt], &bh[ng >> 1][(ng & 1) * 2]);
        }
        __syncthreads();
        if (c + 2 < NC) load_chunk(c + 2, c & 1);
    }

    const int tr = lane >> 2, tc = (lane & 3) * 2;
#pragma unroll
    for (int mt = 0; mt < 2; mt++) {
        int row = m0 + wm * 32 + mt * 16 + tr;
#pragma unroll
        for (int ng = 0; ng < 8; ng++) {
            int col = n0 + wn * 64 + ng * 8 + tc;
            *(float2*)(C + (size_t)row * N + col) =
                make_float2(acc[mt][ng][0], acc[mt][ng][1]);
            *(float2*)(C + (size_t)(row + 8) * N + col) =
                make_float2(acc[mt][ng][2], acc[mt][ng][3]);
        }
    }
}

// ---------------------------------------------------------------------------
// Flash attention, fp32 SIMT, causal + sqrt-ALiBi.
// R3 version + (a) smem sqrt table kills MUFU sqrt, (b) hi/lo bf16 epilogue.
// ---------------------------------------------------------------------------
__global__ __launch_bounds__(256, 2) void attn_kernel(
    const float* __restrict__ qkv, const int* __restrict__ pos,
    __nv_bfloat16* __restrict__ oh, __nv_bfloat16* __restrict__ ol)
{
    extern __shared__ __align__(16) float smem_f[];
    float* Qs  = smem_f;                       // 64*128
    float* KVs = smem_f + 8192;                // 64*128 (K, then V)
    float* Ps  = smem_f + 16384;               // 64*65
    float* m_s = smem_f + 16384 + 64 * 65;
    float* l_s = m_s + 64;
    int*   pq  = (int*)(l_s + 64);
    int*   pk  = pq + 64;
    float* tab = (float*)(pk + 64);            // 2048 sqrt table

    const int tid = threadIdx.x;
    const int sx = tid & 15, sy = tid >> 4;
    const int qt = gridDim.x - 1 - blockIdx.x;
    const int h  = blockIdx.y;
    const int g  = h >> 2;
    const int q0 = qt * BQ;
    const float nslope = -exp2f(-0.25f * (float)(h + 1));
    const float scale = 0.08838834764831844f;

    const int qoff = h * HD;
    const int koff = Q_SIZE + g * HD;
    const int voff = Q_SIZE + KV_SIZE + g * HD;

    // sqrt table (positions are iota 0..2047 -> dist in [0, 2048))
    for (int i = tid; i < 2048; i += 256) tab[i] = sqrtf((float)i);

    for (int f = tid; f < BQ * HD / 4; f += 256) {
        int row = f >> 5, c4 = f & 31;
        float4 v = *(const float4*)(qkv + (size_t)(q0 + row) * QKV_W + qoff + (c4 << 2));
        v.x *= scale; v.y *= scale; v.z *= scale; v.w *= scale;
        *(float4*)(Qs + row * HD + (c4 << 2)) = v;
    }
    if (tid < BQ) {
        pq[tid]  = pos[q0 + tid];
        m_s[tid] = -FLT_MAX;
        l_s[tid] = 0.f;
    }
    float acc[4][8];
#pragma unroll
    for (int i = 0; i < 4; i++)
#pragma unroll
        for (int j = 0; j < 8; j++) acc[i][j] = 0.f;
    __syncthreads();

    for (int kt = 0; kt <= qt; kt++) {
        const int k0 = kt * BK;
        for (int f = tid; f < BK * HD / 4; f += 256) {
            int row = f >> 5, c4 = f & 31;
            float4 v = *(const float4*)(qkv + (size_t)(k0 + row) * QKV_W + koff + (c4 << 2));
            *(float4*)(KVs + row * HD + ((c4 ^ (row & 7)) << 2)) = v;
        }
        if (tid < BK) pk[tid] = pos[k0 + tid];
        __syncthreads();

        float s[4][4];
#pragma unroll
        for (int i = 0; i < 4; i++)
#pragma unroll
            for (int j = 0; j < 4; j++) s[i][j] = 0.f;

#pragma unroll 8
        for (int d4 = 0; d4 < 32; d4++) {
            float4 qv[4], kv[4];
            const int swzc = (d4 ^ (sx & 7)) << 2;
#pragma unroll
            for (int i = 0; i < 4; i++)
                qv[i] = *(const float4*)(Qs + (sy * 4 + i) * HD + (d4 << 2));
#pragma unroll
            for (int j = 0; j < 4; j++)
                kv[j] = *(const float4*)(KVs + (sx + (j << 4)) * HD + swzc);
#pragma unroll
            for (int i = 0; i < 4; i++)
#pragma unroll
                for (int j = 0; j < 4; j++) {
                    s[i][j] = fmaf(qv[i].x, kv[j].x, s[i][j]);
                    s[i][j] = fmaf(qv[i].y, kv[j].y, s[i][j]);
                    s[i][j] = fmaf(qv[i].z, kv[j].z, s[i][j]);
                    s[i][j] = fmaf(qv[i].w, kv[j].w, s[i][j]);
                }
        }

        int my_pq[4], my_pk[4];
#pragma unroll
        for (int i = 0; i < 4; i++) my_pq[i] = pq[sy * 4 + i];
#pragma unroll
        for (int j = 0; j < 4; j++) my_pk[j] = pk[sx + 16 * j];

        float rmax[4];
#pragma unroll
        for (int i = 0; i < 4; i++) {
            float mx = -FLT_MAX;
#pragma unroll
            for (int j = 0; j < 4; j++) {
                int dist = my_pq[i] - my_pk[j];
                float bias = tab[dist < 0 ? 0 : dist];      // LDS, not MUFU
                float v = (dist < 0) ? -FLT_MAX
                                     : fmaf(nslope, bias, s[i][j]);
                s[i][j] = v;
                mx = fmaxf(mx, v);
            }
            rmax[i] = mx;
        }
#pragma unroll
        for (int off = 8; off >= 1; off >>= 1)
#pragma unroll
            for (int i = 0; i < 4; i++)
                rmax[i] = fmaxf(rmax[i], __shfl_xor_sync(0xffffffffu, rmax[i], off));

        float fac[4], rsum[4];
#pragma unroll
        for (int i = 0; i < 4; i++) {
            float mo = m_s[sy * 4 + i];
            float mn = fmaxf(mo, rmax[i]);
            fac[i] = __expf(mo - mn);
            float sum = 0.f;
#pragma unroll
            for (int j = 0; j < 4; j++) {
                float p = __expf(s[i][j] - mn);
                s[i][j] = p;
                sum += p;
            }
            rsum[i] = sum;
            rmax[i] = mn;
        }
#pragma unroll
        for (int off = 8; off >= 1; off >>= 1)
#pragma unroll
            for (int i = 0; i < 4; i++)
                rsum[i] += __shfl_xor_sync(0xffffffffu, rsum[i], off);

        if (sx == 0) {
#pragma unroll
            for (int i = 0; i < 4; i++) {
                int r = sy * 4 + i;
                m_s[r] = rmax[i];
                l_s[r] = l_s[r] * fac[i] + rsum[i];
            }
        }
#pragma unroll
        for (int i = 0; i < 4; i++)
#pragma unroll
            for (int j = 0; j < 4; j++)
                Ps[(sy * 4 + i) * 65 + sx + 16 * j] = s[i][j];
        __syncthreads();

        for (int f = tid; f < BK * HD / 4; f += 256) {
            int row = f >> 5, c4 = f & 31;
            float4 v = *(const float4*)(qkv + (size_t)(k0 + row) * QKV_W + voff + (c4 << 2));
            *(float4*)(KVs + row * HD + (c4 << 2)) = v;
        }
        __syncthreads();

#pragma unroll
        for (int i = 0; i < 4; i++)
#pragma unroll
            for (int j = 0; j < 8; j++) acc[i][j] *= fac[i];

#pragma unroll 4
        for (int k = 0; k < BK; k++) {
            float4 v0 = *(const float4*)(KVs + k * HD + sx * 8);
            float4 v1 = *(const float4*)(KVs + k * HD + sx * 8 + 4);
            float pr[4];
#pragma unroll
            for (int i = 0; i < 4; i++) pr[i] = Ps[(sy * 4 + i) * 65 + k];
#pragma unroll
            for (int i = 0; i < 4; i++) {
                acc[i][0] = fmaf(pr[i], v0.x, acc[i][0]);
                acc[i][1] = fmaf(pr[i], v0.y, acc[i][1]);
                acc[i][2] = fmaf(pr[i], v0.z, acc[i][2]);
                acc[i][3] = fmaf(pr[i], v0.w, acc[i][3]);
                acc[i][4] = fmaf(pr[i], v1.x, acc[i][4]);
                acc[i][5] = fmaf(pr[i], v1.y, acc[i][5]);
                acc[i][6] = fmaf(pr[i], v1.z, acc[i][6]);
                acc[i][7] = fmaf(pr[i], v1.w, acc[i][7]);
            }
        }
        __syncthreads();
    }

    // epilogue: normalize, hi/lo split, store bf16 (same bytes as fp32)
#pragma unroll
    for (int i = 0; i < 4; i++) {
        float linv = 1.f / l_s[sy * 4 + i];
        size_t off = (size_t)(q0 + sy * 4 + i) * Q_SIZE + h * HD + sx * 8;
        uint4 hv, lv;
        split2(acc[i][0] * linv, acc[i][1] * linv, hv.x, lv.x);
        split2(acc[i][2] * linv, acc[i][3] * linv, hv.y, lv.y);
        split2(acc[i][4] * linv, acc[i][5] * linv, hv.z, lv.z);
        split2(acc[i][6] * linv, acc[i][7] * linv, hv.w, lv.w);
        *(uint4*)(oh + off) = hv;
        *(uint4*)(ol + off) = lv;
    }
}

// ---------------------------------------------------------------------------
extern "C" void kernel_launch(void* const* d_in, const int* in_sizes, int n_in,
                              void* d_out, int out_size)
{
    (void)in_sizes; (void)n_in; (void)out_size;
    const int*   pos  = (const int*)d_in[0];
    const float* hs   = (const float*)d_in[1];
    const float* wqkv = (const float*)d_in[2];
    const float* wo   = (const float*)d_in[3];
    float* out = (float*)d_out;

    float *qkv_buf;
    __nv_bfloat16 *hs_h, *hs_l, *wq_h, *wq_l, *wo_h, *wo_l, *at_h, *at_l;
    cudaGetSymbolAddress((void**)&qkv_buf, g_qkv);
    cudaGetSymbolAddress((void**)&hs_h, g_hs_h);
    cudaGetSymbolAddress((void**)&hs_l, g_hs_l);
    cudaGetSymbolAddress((void**)&wq_h, g_wqkv_h);
    cudaGetSymbolAddress((void**)&wq_l, g_wqkv_l);
    cudaGetSymbolAddress((void**)&wo_h, g_wo_h);
    cudaGetSymbolAddress((void**)&wo_l, g_wo_l);
    cudaGetSymbolAddress((void**)&at_h, g_at_h);
    cudaGetSymbolAddress((void**)&at_l, g_at_l);

    cudaFuncSetAttribute(gemm_mma, cudaFuncAttributeMaxDynamicSharedMemorySize,
                         GEMM_SMEM);

    // 0) split inputs to bf16 hi/lo
    split_kernel<<<(S_LEN * HID) / 1024, 256>>>(hs, hs_h, hs_l, S_LEN * HID);
    split_kernel<<<(QKV_W * HID) / 1024, 256>>>(wqkv, wq_h, wq_l, QKV_W * HID);
    split_kernel<<<(HID * HID) / 1024, 256>>>(wo, wo_h, wo_l, HID * HID);

    // 1) QKV projection (HMMA) -> fp32
    gemm_mma<<<dim3(QKV_W / 128, S_LEN / 128), 256, GEMM_SMEM>>>(
        hs_h, hs_l, wq_h, wq_l, qkv_buf, S_LEN, QKV_W, HID);

    // 2) Attention (fp32 SIMT, sqrt table) -> hi/lo bf16 directly
    const int attn_smem = (8192 + 8192 + 64 * 65 + 64 * 4 + 2048) * 4;  // 91392
    cudaFuncSetAttribute(attn_kernel, cudaFuncAttributeMaxDynamicSharedMemorySize,
                         attn_smem);
    attn_kernel<<<dim3(S_LEN / BQ, NH), 256, attn_smem>>>(qkv_buf, pos,
                                                          at_h, at_l);

    // 3) O-projection (HMMA) -> fp32 out
    gemm_mma<<<dim3(HID / 128, S_LEN / 128), 256, GEMM_SMEM>>>(
        at_h, at_l, wo_h, wo_l, out, S_LEN, HID, HID);
}

// round 12
// speedup vs baseline: 1.0061x; 1.0061x over previous
#include <cuda_runtime.h>
#include <cuda_bf16.h>
#include <math.h>
#include <float.h>
#include <stdint.h>

#define S_LEN  2048
#define HID    4096
#define NH     32
#define HD     128
#define QKV_W  12288
#define Q_SIZE 4096
#define KV_SIZE 1024
#define BQ 64
#define BK 64

// GEMM tile config: CTA 128x128, K chunk 32 (bf16), 2 stages
#define CHK 32
#define STAGE 32768
#define AH_OFF 0
#define AL_OFF 8192
#define BH_OFF 16384
#define BL_OFF 24576
#define GEMM_SMEM (2 * STAGE)

// ---------------------------------------------------------------------------
// Scratch (device globals: allocation-free rule)
// ---------------------------------------------------------------------------
__device__ __align__(256) float g_qkv[(size_t)S_LEN * QKV_W];
__device__ __align__(256) __nv_bfloat16 g_hs_h[(size_t)S_LEN * HID];
__device__ __align__(256) __nv_bfloat16 g_hs_l[(size_t)S_LEN * HID];
__device__ __align__(256) __nv_bfloat16 g_wqkv_h[(size_t)QKV_W * HID];
__device__ __align__(256) __nv_bfloat16 g_wqkv_l[(size_t)QKV_W * HID];
__device__ __align__(256) __nv_bfloat16 g_wo_h[(size_t)HID * HID];
__device__ __align__(256) __nv_bfloat16 g_wo_l[(size_t)HID * HID];
__device__ __align__(256) __nv_bfloat16 g_at_h[(size_t)S_LEN * Q_SIZE];
__device__ __align__(256) __nv_bfloat16 g_at_l[(size_t)S_LEN * Q_SIZE];

// ---------------------------------------------------------------------------
// PTX helpers (plain sm_80-era PTX)
// ---------------------------------------------------------------------------
__device__ __forceinline__ uint32_t smem_u32(const void* p) {
    uint32_t a;
    asm("{ .reg .u64 t; cvta.to.shared.u64 t, %1; cvt.u32.u64 %0, t; }"
        : "=r"(a) : "l"(p));
    return a;
}
__device__ __forceinline__ void cpasync16(uint32_t dst, const void* src) {
    asm volatile("cp.async.cg.shared.global [%0], [%1], 16;"
                 :: "r"(dst), "l"(src) : "memory");
}
__device__ __forceinline__ void ldsm4(uint32_t* r, uint32_t addr) {
    asm volatile("ldmatrix.sync.aligned.m8n8.x4.shared.b16 {%0,%1,%2,%3}, [%4];"
                 : "=r"(r[0]), "=r"(r[1]), "=r"(r[2]), "=r"(r[3]) : "r"(addr));
}
__device__ __forceinline__ void mma_bf16(float* d, const uint32_t* a,
                                         const uint32_t* b) {
    asm volatile(
        "mma.sync.aligned.m16n8k16.row.col.f32.bf16.bf16.f32 "
        "{%0,%1,%2,%3}, {%4,%5,%6,%7}, {%8,%9}, {%0,%1,%2,%3};"
        : "+f"(d[0]), "+f"(d[1]), "+f"(d[2]), "+f"(d[3])
        : "r"(a[0]), "r"(a[1]), "r"(a[2]), "r"(a[3]), "r"(b[0]), "r"(b[1]));
}
__device__ __forceinline__ uint32_t swz(int row, int seg) {
    return row * 64 + ((seg ^ ((row >> 1) & 3)) << 4);
}
__device__ __forceinline__ void split2(float v0, float v1,
                                       uint32_t& hp, uint32_t& lp) {
    uint32_t u0 = __float_as_uint(v0) & 0xFFFF0000u;
    uint32_t u1 = __float_as_uint(v1) & 0xFFFF0000u;
    hp = (u0 >> 16) | u1;
    float r0 = v0 - __uint_as_float(u0);
    float r1 = v1 - __uint_as_float(u1);
    asm("cvt.rn.bf16x2.f32 %0, %1, %2;" : "=r"(lp) : "f"(r1), "f"(r0));
}

// ---------------------------------------------------------------------------
// fp32 -> bf16 hi/lo split
// ---------------------------------------------------------------------------
__global__ __launch_bounds__(256) void split_kernel(
    const float* __restrict__ x, __nv_bfloat16* __restrict__ hi,
    __nv_bfloat16* __restrict__ lo, int n)
{
    int i = (blockIdx.x * 256 + threadIdx.x) * 4;
    if (i >= n) return;
    float4 v = *(const float4*)(x + i);
    uint32_t h01, l01, h23, l23;
    split2(v.x, v.y, h01, l01);
    split2(v.z, v.w, h23, l23);
    *(uint2*)(hi + i) = make_uint2(h01, h23);
    *(uint2*)(lo + i) = make_uint2(l01, l23);
}

// ---------------------------------------------------------------------------
// HMMA split-bf16 GEMM NT (exact R3 version — proven 70% tensor)
// ---------------------------------------------------------------------------
__global__ __launch_bounds__(256, 2) void gemm_mma(
    const __nv_bfloat16* __restrict__ Ah, const __nv_bfloat16* __restrict__ Al,
    const __nv_bfloat16* __restrict__ Bh, const __nv_bfloat16* __restrict__ Bl,
    float* __restrict__ C, int M, int N, int K)
{
    extern __shared__ __align__(128) char smem_g[];
    const uint32_t sb = smem_u32(smem_g);
    const int tid  = threadIdx.x;
    const int lane = tid & 31, warp = tid >> 5;
    const int wm = warp >> 1, wn = warp & 1;
    const int m0 = blockIdx.y << 7, n0 = blockIdx.x << 7;
    const int NC = K / CHK;

    const int a_row = lane & 15;
    const int a_kh  = lane >> 4;
    const int b_row = (lane & 7) + ((lane & 16) >> 1);
    const int b_kh  = (lane >> 3) & 1;

    float acc[2][8][4];
#pragma unroll
    for (int mt = 0; mt < 2; mt++)
#pragma unroll
        for (int ng = 0; ng < 8; ng++)
#pragma unroll
            for (int r = 0; r < 4; r++) acc[mt][ng][r] = 0.f;

    auto load_chunk = [&](int c, int s) {
        const uint32_t st = sb + s * STAGE;
        const int k0 = c * CHK;
#pragma unroll
        for (int i = 0; i < 2; i++) {
            int idx = tid + i * 256;
            int row = idx >> 2, seg = idx & 3;
            uint32_t so = swz(row, seg);
            size_t ga = (size_t)(m0 + row) * K + k0 + seg * 8;
            size_t gb = (size_t)(n0 + row) * K + k0 + seg * 8;
            cpasync16(st + AH_OFF + so, Ah + ga);
            cpasync16(st + AL_OFF + so, Al + ga);
            cpasync16(st + BH_OFF + so, Bh + gb);
            cpasync16(st + BL_OFF + so, Bl + gb);
        }
        asm volatile("cp.async.commit_group;" ::: "memory");
    };

    load_chunk(0, 0);
    if (NC > 1) load_chunk(1, 1);

    for (int c = 0; c < NC; c++) {
        if (c + 1 < NC)
            asm volatile("cp.async.wait_group 1;" ::: "memory");
        else
            asm volatile("cp.async.wait_group 0;" ::: "memory");
        __syncthreads();

        const uint32_t st = sb + (c & 1) * STAGE;
#pragma unroll
        for (int kk = 0; kk < 2; kk++) {
            uint32_t ah[2][4], al[2][4], bh[4][4], bl[4][4];
#pragma unroll
            for (int mt = 0; mt < 2; mt++) {
                int r = wm * 32 + mt * 16 + a_row;
                ldsm4(ah[mt], st + AH_OFF + swz(r, kk * 2 + a_kh));
            }
#pragma unroll
            for (int g = 0; g < 4; g++) {
                int r = wn * 64 + g * 16 + b_row;
                ldsm4(bh[g], st + BH_OFF + swz(r, kk * 2 + b_kh));
            }
#pragma unroll
            for (int mt = 0; mt < 2; mt++)
#pragma unroll
                for (int ng = 0; ng < 8; ng++)
                    mma_bf16(acc[mt][ng], ah[mt], &bh[ng >> 1][(ng & 1) * 2]);
#pragma unroll
            for (int g = 0; g < 4; g++) {
                int r = wn * 64 + g * 16 + b_row;
                ldsm4(bl[g], st + BL_OFF + swz(r, kk * 2 + b_kh));
            }
#pragma unroll
            for (int mt = 0; mt < 2; mt++)
#pragma unroll
                for (int ng = 0; ng < 8; ng++)
                    mma_bf16(acc[mt][ng], ah[mt], &bl[ng >> 1][(ng & 1) * 2]);
#pragma unroll
            for (int mt = 0; mt < 2; mt++) {
                int r = wm * 32 + mt * 16 + a_row;
                ldsm4(al[mt], st + AL_OFF + swz(r, kk * 2 + a_kh));
            }
#pragma unroll
            for (int mt = 0; mt < 2; mt++)
#pragma unroll
                for (int ng = 0; ng < 8; ng++)
                    mma_bf16(acc[mt][ng], al[mt], &bh[ng >> 1][(ng & 1) * 2]);
        }
        __syncthreads();
        if (c + 2 < NC) load_chunk(c + 2, c & 1);
    }

    const int tr = lane >> 2, tc = (lane & 3) * 2;
#pragma unroll
    for (int mt = 0; mt < 2; mt++) {
        int row = m0 + wm * 32 + mt * 16 + tr;
#pragma unroll
        for (int ng = 0; ng < 8; ng++) {
            int col = n0 + wn * 64 + ng * 8 + tc;
            *(float2*)(C + (size_t)row * N + col) =
                make_float2(acc[mt][ng][0], acc[mt][ng][1]);
            *(float2*)(C + (size_t)(row + 8) * N + col) =
                make_float2(acc[mt][ng][2], acc[mt][ng][3]);
        }
    }
}

// ---------------------------------------------------------------------------
// Flash attention, fp32 SIMT, causal + sqrt-ALiBi.
// R3 version + (a) smem sqrt table kills MUFU sqrt, (b) hi/lo bf16 epilogue.
// ---------------------------------------------------------------------------
__global__ __launch_bounds__(256, 2) void attn_kernel(
    const float* __restrict__ qkv, const int* __restrict__ pos,
    __nv_bfloat16* __restrict__ oh, __nv_bfloat16* __restrict__ ol)
{
    extern __shared__ __align__(16) float smem_f[];
    float* Qs  = smem_f;                       // 64*128
    float* KVs = smem_f + 8192;                // 64*128 (K, then V)
    float* Ps  = smem_f + 16384;               // 64*65
    float* m_s = smem_f + 16384 + 64 * 65;
    float* l_s = m_s + 64;
    int*   pq  = (int*)(l_s + 64);
    int*   pk  = pq + 64;
    float* tab = (float*)(pk + 64);            // 2048 sqrt table

    const int tid = threadIdx.x;
    const int sx = tid & 15, sy = tid >> 4;
    const int qt = gridDim.x - 1 - blockIdx.x;
    const int h  = blockIdx.y;
    const int g  = h >> 2;
    const int q0 = qt * BQ;
    const float nslope = -exp2f(-0.25f * (float)(h + 1));
    const float scale = 0.08838834764831844f;

    const int qoff = h * HD;
    const int koff = Q_SIZE + g * HD;
    const int voff = Q_SIZE + KV_SIZE + g * HD;

    // sqrt table (positions are iota 0..2047 -> dist in [0, 2048))
    for (int i = tid; i < 2048; i += 256) tab[i] = sqrtf((float)i);

    for (int f = tid; f < BQ * HD / 4; f += 256) {
        int row = f >> 5, c4 = f & 31;
        float4 v = *(const float4*)(qkv + (size_t)(q0 + row) * QKV_W + qoff + (c4 << 2));
        v.x *= scale; v.y *= scale; v.z *= scale; v.w *= scale;
        *(float4*)(Qs + row * HD + (c4 << 2)) = v;
    }
    if (tid < BQ) {
        pq[tid]  = pos[q0 + tid];
        m_s[tid] = -FLT_MAX;
        l_s[tid] = 0.f;
    }
    float acc[4][8];
#pragma unroll
    for (int i = 0; i < 4; i++)
#pragma unroll
        for (int j = 0; j < 8; j++) acc[i][j] = 0.f;
    __syncthreads();

    for (int kt = 0; kt <= qt; kt++) {
        const int k0 = kt * BK;
        for (int f = tid; f < BK * HD / 4; f += 256) {
            int row = f >> 5, c4 = f & 31;
            float4 v = *(const float4*)(qkv + (size_t)(k0 + row) * QKV_W + koff + (c4 << 2));
            *(float4*)(KVs + row * HD + ((c4 ^ (row & 7)) << 2)) = v;
        }
        if (tid < BK) pk[tid] = pos[k0 + tid];
        __syncthreads();

        float s[4][4];
#pragma unroll
        for (int i = 0; i < 4; i++)
#pragma unroll
            for (int j = 0; j < 4; j++) s[i][j] = 0.f;

#pragma unroll 8
        for (int d4 = 0; d4 < 32; d4++) {
            float4 qv[4], kv[4];
            const int swzc = (d4 ^ (sx & 7)) << 2;
#pragma unroll
            for (int i = 0; i < 4; i++)
                qv[i] = *(const float4*)(Qs + (sy * 4 + i) * HD + (d4 << 2));
#pragma unroll
            for (int j = 0; j < 4; j++)
                kv[j] = *(const float4*)(KVs + (sx + (j << 4)) * HD + swzc);
#pragma unroll
            for (int i = 0; i < 4; i++)
#pragma unroll
                for (int j = 0; j < 4; j++) {
                    s[i][j] = fmaf(qv[i].x, kv[j].x, s[i][j]);
                    s[i][j] = fmaf(qv[i].y, kv[j].y, s[i][j]);
                    s[i][j] = fmaf(qv[i].z, kv[j].z, s[i][j]);
                    s[i][j] = fmaf(qv[i].w, kv[j].w, s[i][j]);
                }
        }

        int my_pq[4], my_pk[4];
#pragma unroll
        for (int i = 0; i < 4; i++) my_pq[i] = pq[sy * 4 + i];
#pragma unroll
        for (int j = 0; j < 4; j++) my_pk[j] = pk[sx + 16 * j];

        float rmax[4];
#pragma unroll
        for (int i = 0; i < 4; i++) {
            float mx = -FLT_MAX;
#pragma unroll
            for (int j = 0; j < 4; j++) {
                int dist = my_pq[i] - my_pk[j];
                float bias = tab[dist < 0 ? 0 : dist];      // LDS, not MUFU
                float v = (dist < 0) ? -FLT_MAX
                                     : fmaf(nslope, bias, s[i][j]);
                s[i][j] = v;
                mx = fmaxf(mx, v);
            }
            rmax[i] = mx;
        }
#pragma unroll
        for (int off = 8; off >= 1; off >>= 1)
#pragma unroll
            for (int i = 0; i < 4; i++)
                rmax[i] = fmaxf(rmax[i], __shfl_xor_sync(0xffffffffu, rmax[i], off));

        float fac[4], rsum[4];
#pragma unroll
        for (int i = 0; i < 4; i++) {
            float mo = m_s[sy * 4 + i];
            float mn = fmaxf(mo, rmax[i]);
            fac[i] = __expf(mo - mn);
            float sum = 0.f;
#pragma unroll
            for (int j = 0; j < 4; j++) {
                float p = __expf(s[i][j] - mn);
                s[i][j] = p;
                sum += p;
            }
            rsum[i] = sum;
            rmax[i] = mn;
        }
#pragma unroll
        for (int off = 8; off >= 1; off >>= 1)
#pragma unroll
            for (int i = 0; i < 4; i++)
                rsum[i] += __shfl_xor_sync(0xffffffffu, rsum[i], off);

        if (sx == 0) {
#pragma unroll
            for (int i = 0; i < 4; i++) {
                int r = sy * 4 + i;
                m_s[r] = rmax[i];
                l_s[r] = l_s[r] * fac[i] + rsum[i];
            }
        }
#pragma unroll
        for (int i = 0; i < 4; i++)
#pragma unroll
            for (int j = 0; j < 4; j++)
                Ps[(sy * 4 + i) * 65 + sx + 16 * j] = s[i][j];
        __syncthreads();

        for (int f = tid; f < BK * HD / 4; f += 256) {
            int row = f >> 5, c4 = f & 31;
            float4 v = *(const float4*)(qkv + (size_t)(k0 + row) * QKV_W + voff + (c4 << 2));
            *(float4*)(KVs + row * HD + (c4 << 2)) = v;
        }
        __syncthreads();

#pragma unroll
        for (int i = 0; i < 4; i++)
#pragma unroll
            for (int j = 0; j < 8; j++) acc[i][j] *= fac[i];

#pragma unroll 4
        for (int k = 0; k < BK; k++) {
            float4 v0 = *(const float4*)(KVs + k * HD + sx * 8);
            float4 v1 = *(const float4*)(KVs + k * HD + sx * 8 + 4);
            float pr[4];
#pragma unroll
            for (int i = 0; i < 4; i++) pr[i] = Ps[(sy * 4 + i) * 65 + k];
#pragma unroll
            for (int i = 0; i < 4; i++) {
                acc[i][0] = fmaf(pr[i], v0.x, acc[i][0]);
                acc[i][1] = fmaf(pr[i], v0.y, acc[i][1]);
                acc[i][2] = fmaf(pr[i], v0.z, acc[i][2]);
                acc[i][3] = fmaf(pr[i], v0.w, acc[i][3]);
                acc[i][4] = fmaf(pr[i], v1.x, acc[i][4]);
                acc[i][5] = fmaf(pr[i], v1.y, acc[i][5]);
                acc[i][6] = fmaf(pr[i], v1.z, acc[i][6]);
                acc[i][7] = fmaf(pr[i], v1.w, acc[i][7]);
            }
        }
        __syncthreads();
    }

    // epilogue: normalize, hi/lo split, store bf16 (same bytes as fp32)
#pragma unroll
    for (int i = 0; i < 4; i++) {
        float linv = 1.f / l_s[sy * 4 + i];
        size_t off = (size_t)(q0 + sy * 4 + i) * Q_SIZE + h * HD + sx * 8;
        uint4 hv, lv;
        split2(acc[i][0] * linv, acc[i][1] * linv, hv.x, lv.x);
        split2(acc[i][2] * linv, acc[i][3] * linv, hv.y, lv.y);
        split2(acc[i][4] * linv, acc[i][5] * linv, hv.z, lv.z);
        split2(acc[i][6] * linv, acc[i][7] * linv, hv.w, lv.w);
        *(uint4*)(oh + off) = hv;
        *(uint4*)(ol + off) = lv;
    }
}

// ---------------------------------------------------------------------------
extern "C" void kernel_launch(void* const* d_in, const int* in_sizes, int n_in,
                              void* d_out, int out_size)
{
    (void)in_sizes; (void)n_in; (void)out_size;
    const int*   pos  = (const int*)d_in[0];
    const float* hs   = (const float*)d_in[1];
    const float* wqkv = (const float*)d_in[2];
    const float* wo   = (const float*)d_in[3];
    float* out = (float*)d_out;

    float *qkv_buf;
    __nv_bfloat16 *hs_h, *hs_l, *wq_h, *wq_l, *wo_h, *wo_l, *at_h, *at_l;
    cudaGetSymbolAddress((void**)&qkv_buf, g_qkv);
    cudaGetSymbolAddress((void**)&hs_h, g_hs_h);
    cudaGetSymbolAddress((void**)&hs_l, g_hs_l);
    cudaGetSymbolAddress((void**)&wq_h, g_wqkv_h);
    cudaGetSymbolAddress((void**)&wq_l, g_wqkv_l);
    cudaGetSymbolAddress((void**)&wo_h, g_wo_h);
    cudaGetSymbolAddress((void**)&wo_l, g_wo_l);
    cudaGetSymbolAddress((void**)&at_h, g_at_h);
    cudaGetSymbolAddress((void**)&at_l, g_at_l);

    cudaFuncSetAttribute(gemm_mma, cudaFuncAttributeMaxDynamicSharedMemorySize,
                         GEMM_SMEM);

    // 0) split inputs to bf16 hi/lo
    split_kernel<<<(S_LEN * HID) / 1024, 256>>>(hs, hs_h, hs_l, S_LEN * HID);
    split_kernel<<<(QKV_W * HID) / 1024, 256>>>(wqkv, wq_h, wq_l, QKV_W * HID);
    split_kernel<<<(HID * HID) / 1024, 256>>>(wo, wo_h, wo_l, HID * HID);

    // 1) QKV projection (HMMA) -> fp32
    gemm_mma<<<dim3(QKV_W / 128, S_LEN / 128), 256, GEMM_SMEM>>>(
        hs_h, hs_l, wq_h, wq_l, qkv_buf, S_LEN, QKV_W, HID);

    // 2) Attention (fp32 SIMT, sqrt table) -> hi/lo bf16 directly
    const int attn_smem = (8192 + 8192 + 64 * 65 + 64 * 4 + 2048) * 4;  // 91392
    cudaFuncSetAttribute(attn_kernel, cudaFuncAttributeMaxDynamicSharedMemorySize,
                         attn_smem);
    attn_kernel<<<dim3(S_LEN / BQ, NH), 256, attn_smem>>>(qkv_buf, pos,
                                                          at_h, at_l);

    // 3) O-projection (HMMA) -> fp32 out
    gemm_mma<<<dim3(HID / 128, S_LEN / 128), 256, GEMM_SMEM>>>(
        at_h, at_l, wo_h, wo_l, out, S_LEN, HID, HID);
}

// round 13
// speedup vs baseline: 1.3699x; 1.3617x over previous
#include <cuda_runtime.h>
#include <cuda_bf16.h>
#include <math.h>
#include <float.h>
#include <stdint.h>

#define S_LEN  2048
#define HID    4096
#define NH     32
#define HD     128
#define QKV_W  12288
#define Q_SIZE 4096
#define KV_SIZE 1024

// GEMM tile config: CTA 128x128, K chunk 32 (bf16), 2 stages
#define CHK 32
#define STAGE 32768
#define AH_OFF 0
#define AL_OFF 8192
#define BH_OFF 16384
#define BL_OFF 24576
#define GEMM_SMEM (2 * STAGE)

// Attention (tensor) config: 128 threads, BQ=64 q rows, BK=16 keys
#define ABQ 64
#define ABK 16
#define A_QH   0
#define A_QL   16384
#define A_ST   32768          // 2 stages x 16KB
#define A_STG  16384
#define A_KH   0
#define A_KL   4096
#define A_VH   8192
#define A_VL   12288
#define A_TAB  65536
#define A_PQ   73728
#define A_PK   73984          // 2 x 64B
#define A_SMEM 74112

// ---------------------------------------------------------------------------
// Scratch (device globals: allocation-free rule)
// ---------------------------------------------------------------------------
__device__ __align__(256) __nv_bfloat16 g_hs_h[(size_t)S_LEN * HID];
__device__ __align__(256) __nv_bfloat16 g_hs_l[(size_t)S_LEN * HID];
__device__ __align__(256) __nv_bfloat16 g_wqkv_h[(size_t)QKV_W * HID];
__device__ __align__(256) __nv_bfloat16 g_wqkv_l[(size_t)QKV_W * HID];
__device__ __align__(256) __nv_bfloat16 g_wo_h[(size_t)HID * HID];
__device__ __align__(256) __nv_bfloat16 g_wo_l[(size_t)HID * HID];
__device__ __align__(256) __nv_bfloat16 g_qkv_h[(size_t)S_LEN * QKV_W];
__device__ __align__(256) __nv_bfloat16 g_qkv_l[(size_t)S_LEN * QKV_W];
__device__ __align__(256) __nv_bfloat16 g_at_h[(size_t)S_LEN * Q_SIZE];
__device__ __align__(256) __nv_bfloat16 g_at_l[(size_t)S_LEN * Q_SIZE];

// ---------------------------------------------------------------------------
// PTX helpers (plain sm_80-era PTX)
// ---------------------------------------------------------------------------
__device__ __forceinline__ uint32_t smem_u32(const void* p) {
    uint32_t a;
    asm("{ .reg .u64 t; cvta.to.shared.u64 t, %1; cvt.u32.u64 %0, t; }"
        : "=r"(a) : "l"(p));
    return a;
}
__device__ __forceinline__ void cpasync16(uint32_t dst, const void* src) {
    asm volatile("cp.async.cg.shared.global [%0], [%1], 16;"
                 :: "r"(dst), "l"(src) : "memory");
}
__device__ __forceinline__ void cpasync4(uint32_t dst, const void* src) {
    asm volatile("cp.async.ca.shared.global [%0], [%1], 4;"
                 :: "r"(dst), "l"(src) : "memory");
}
__device__ __forceinline__ void ldsm4(uint32_t* r, uint32_t addr) {
    asm volatile("ldmatrix.sync.aligned.m8n8.x4.shared.b16 {%0,%1,%2,%3}, [%4];"
                 : "=r"(r[0]), "=r"(r[1]), "=r"(r[2]), "=r"(r[3]) : "r"(addr));
}
__device__ __forceinline__ void ldsm4t(uint32_t* r, uint32_t addr) {
    asm volatile("ldmatrix.sync.aligned.m8n8.x4.trans.shared.b16 {%0,%1,%2,%3}, [%4];"
                 : "=r"(r[0]), "=r"(r[1]), "=r"(r[2]), "=r"(r[3]) : "r"(addr));
}
__device__ __forceinline__ void mma_bf16(float* d, const uint32_t* a,
                                         const uint32_t* b) {
    asm volatile(
        "mma.sync.aligned.m16n8k16.row.col.f32.bf16.bf16.f32 "
        "{%0,%1,%2,%3}, {%4,%5,%6,%7}, {%8,%9}, {%0,%1,%2,%3};"
        : "+f"(d[0]), "+f"(d[1]), "+f"(d[2]), "+f"(d[3])
        : "r"(a[0]), "r"(a[1]), "r"(a[2]), "r"(a[3]), "r"(b[0]), "r"(b[1]));
}
__device__ __forceinline__ uint32_t swz(int row, int seg) {       // 128B rows
    return row * 64 + ((seg ^ ((row >> 1) & 3)) << 4);
}
__device__ __forceinline__ uint32_t swzA(int row, int chunk) {    // 256B rows
    return row * 256 + ((chunk ^ (row & 7)) << 4);
}
__device__ __forceinline__ void split2(float v0, float v1,
                                       uint32_t& hp, uint32_t& lp) {
    uint32_t u0 = __float_as_uint(v0) & 0xFFFF0000u;
    uint32_t u1 = __float_as_uint(v1) & 0xFFFF0000u;
    hp = (u0 >> 16) | u1;
    float r0 = v0 - __uint_as_float(u0);
    float r1 = v1 - __uint_as_float(u1);
    asm("cvt.rn.bf16x2.f32 %0, %1, %2;" : "=r"(lp) : "f"(r1), "f"(r0));
}

// ---------------------------------------------------------------------------
// fp32 -> bf16 hi/lo split
// ---------------------------------------------------------------------------
__global__ __launch_bounds__(256) void split_kernel(
    const float* __restrict__ x, __nv_bfloat16* __restrict__ hi,
    __nv_bfloat16* __restrict__ lo, int n)
{
    int i = (blockIdx.x * 256 + threadIdx.x) * 4;
    if (i >= n) return;
    float4 v = *(const float4*)(x + i);
    uint32_t h01, l01, h23, l23;
    split2(v.x, v.y, h01, l01);
    split2(v.z, v.w, h23, l23);
    *(uint2*)(hi + i) = make_uint2(h01, h23);
    *(uint2*)(lo + i) = make_uint2(l01, l23);
}

// ---------------------------------------------------------------------------
// HMMA split-bf16 GEMM NT (proven R12 body).
// MODE 0: fp32 out. MODE 1: hi/lo bf16 out, cols < Q_SIZE scaled by 128^-0.5.
// ---------------------------------------------------------------------------
template<int MODE>
__global__ __launch_bounds__(256, 2) void gemm_mma_t(
    const __nv_bfloat16* __restrict__ Ah, const __nv_bfloat16* __restrict__ Al,
    const __nv_bfloat16* __restrict__ Bh, const __nv_bfloat16* __restrict__ Bl,
    float* __restrict__ C, __nv_bfloat16* __restrict__ Ch,
    __nv_bfloat16* __restrict__ Cl, int M, int N, int K)
{
    extern __shared__ __align__(128) char smem_g[];
    const uint32_t sb = smem_u32(smem_g);
    const int tid  = threadIdx.x;
    const int lane = tid & 31, warp = tid >> 5;
    const int wm = warp >> 1, wn = warp & 1;
    const int m0 = blockIdx.y << 7, n0 = blockIdx.x << 7;
    const int NC = K / CHK;

    const int a_row = lane & 15;
    const int a_kh  = lane >> 4;
    const int b_row = (lane & 7) + ((lane & 16) >> 1);
    const int b_kh  = (lane >> 3) & 1;

    float acc[2][8][4];
#pragma unroll
    for (int mt = 0; mt < 2; mt++)
#pragma unroll
        for (int ng = 0; ng < 8; ng++)
#pragma unroll
            for (int r = 0; r < 4; r++) acc[mt][ng][r] = 0.f;

    auto load_chunk = [&](int c, int s) {
        const uint32_t st = sb + s * STAGE;
        const int k0 = c * CHK;
#pragma unroll
        for (int i = 0; i < 2; i++) {
            int idx = tid + i * 256;
            int row = idx >> 2, seg = idx & 3;
            uint32_t so = swz(row, seg);
            size_t ga = (size_t)(m0 + row) * K + k0 + seg * 8;
            size_t gb = (size_t)(n0 + row) * K + k0 + seg * 8;
            cpasync16(st + AH_OFF + so, Ah + ga);
            cpasync16(st + AL_OFF + so, Al + ga);
            cpasync16(st + BH_OFF + so, Bh + gb);
            cpasync16(st + BL_OFF + so, Bl + gb);
        }
        asm volatile("cp.async.commit_group;" ::: "memory");
    };

    load_chunk(0, 0);
    if (NC > 1) load_chunk(1, 1);

    for (int c = 0; c < NC; c++) {
        if (c + 1 < NC)
            asm volatile("cp.async.wait_group 1;" ::: "memory");
        else
            asm volatile("cp.async.wait_group 0;" ::: "memory");
        __syncthreads();

        const uint32_t st = sb + (c & 1) * STAGE;
#pragma unroll
        for (int kk = 0; kk < 2; kk++) {
            uint32_t ah[2][4], al[2][4], bh[4][4], bl[4][4];
#pragma unroll
            for (int mt = 0; mt < 2; mt++) {
                int r = wm * 32 + mt * 16 + a_row;
                ldsm4(ah[mt], st + AH_OFF + swz(r, kk * 2 + a_kh));
            }
#pragma unroll
            for (int g = 0; g < 4; g++) {
                int r = wn * 64 + g * 16 + b_row;
                ldsm4(bh[g], st + BH_OFF + swz(r, kk * 2 + b_kh));
            }
#pragma unroll
            for (int mt = 0; mt < 2; mt++)
#pragma unroll
                for (int ng = 0; ng < 8; ng++)
                    mma_bf16(acc[mt][ng], ah[mt], &bh[ng >> 1][(ng & 1) * 2]);
#pragma unroll
            for (int g = 0; g < 4; g++) {
                int r = wn * 64 + g * 16 + b_row;
                ldsm4(bl[g], st + BL_OFF + swz(r, kk * 2 + b_kh));
            }
#pragma unroll
            for (int mt = 0; mt < 2; mt++)
#pragma unroll
                for (int ng = 0; ng < 8; ng++)
                    mma_bf16(acc[mt][ng], ah[mt], &bl[ng >> 1][(ng & 1) * 2]);
#pragma unroll
            for (int mt = 0; mt < 2; mt++) {
                int r = wm * 32 + mt * 16 + a_row;
                ldsm4(al[mt], st + AL_OFF + swz(r, kk * 2 + a_kh));
            }
#pragma unroll
            for (int mt = 0; mt < 2; mt++)
#pragma unroll
                for (int ng = 0; ng < 8; ng++)
                    mma_bf16(acc[mt][ng], al[mt], &bh[ng >> 1][(ng & 1) * 2]);
        }
        __syncthreads();
        if (c + 2 < NC) load_chunk(c + 2, c & 1);
    }

    const int tr = lane >> 2, tc = (lane & 3) * 2;
    const float qsc = 0.08838834764831844f;
#pragma unroll
    for (int mt = 0; mt < 2; mt++) {
        int row = m0 + wm * 32 + mt * 16 + tr;
#pragma unroll
        for (int ng = 0; ng < 8; ng++) {
            int col = n0 + wn * 64 + ng * 8 + tc;
            if (MODE == 0) {
                *(float2*)(C + (size_t)row * N + col) =
                    make_float2(acc[mt][ng][0], acc[mt][ng][1]);
                *(float2*)(C + (size_t)(row + 8) * N + col) =
                    make_float2(acc[mt][ng][2], acc[mt][ng][3]);
            } else {
                float sc = (col < Q_SIZE) ? qsc : 1.f;
                uint32_t hp, lp;
                split2(acc[mt][ng][0] * sc, acc[mt][ng][1] * sc, hp, lp);
                *(uint32_t*)(Ch + (size_t)row * N + col) = hp;
                *(uint32_t*)(Cl + (size_t)row * N + col) = lp;
                split2(acc[mt][ng][2] * sc, acc[mt][ng][3] * sc, hp, lp);
                *(uint32_t*)(Ch + (size_t)(row + 8) * N + col) = hp;
                *(uint32_t*)(Cl + (size_t)(row + 8) * N + col) = lp;
            }
        }
    }
}

// ---------------------------------------------------------------------------
// Tensor-core flash attention v3: 128 threads / 4 warps, BQ=64, BK=16.
// Each warp owns 16 q-rows x full 128 HD cols; NO duplicated work (exp count
// minimal). bf16 3-term MMAs; smem 74KB -> 3 CTAs/SM (12 warps).
// ---------------------------------------------------------------------------
__global__ __launch_bounds__(128, 3) void attn_tc(
    const __nv_bfloat16* __restrict__ qkvh,
    const __nv_bfloat16* __restrict__ qkvl,
    const int* __restrict__ pos,
    __nv_bfloat16* __restrict__ oh, __nv_bfloat16* __restrict__ ol)
{
    extern __shared__ __align__(1024) char sm[];
    const uint32_t sb = smem_u32(sm);
    const int tid = threadIdx.x, lane = tid & 31, w = tid >> 5;
    const int qt = gridDim.x - 1 - blockIdx.x;       // long CTAs first
    const int h = blockIdx.y, g = h >> 2;
    const int q0 = qt * ABQ;
    const float nslope = -exp2f(-0.25f * (float)(h + 1));
    const int qoff = h * HD;
    const int koff = Q_SIZE + g * HD;
    const int voff = Q_SIZE + KV_SIZE + g * HD;
    const int nt = 4 * (qt + 1);

    float* tab = (float*)(sm + A_TAB);
    for (int i = tid; i < 2048; i += 128) tab[i] = sqrtf((float)i);
    if (tid < ABQ) ((int*)(sm + A_PQ))[tid] = pos[q0 + tid];

    // Q hi/lo tiles (64 x 128 bf16 each)
#pragma unroll
    for (int i = 0; i < 8; i++) {
        int idx = tid + i * 128;
        int row = idx >> 4, ch = idx & 15;
        size_t go = (size_t)(q0 + row) * QKV_W + qoff + ch * 8;
        cpasync16(sb + A_QH + swzA(row, ch), qkvh + go);
        cpasync16(sb + A_QL + swzA(row, ch), qkvl + go);
    }
    asm volatile("cp.async.commit_group;" ::: "memory");
    asm volatile("cp.async.wait_group 0;" ::: "memory");
    __syncthreads();

    const int arow = w * 16 + (lane & 15);
    const int akh = lane >> 4;
    uint32_t qh[8][4];
#pragma unroll
    for (int kk = 0; kk < 8; kk++)
        ldsm4(qh[kk], sb + A_QH + swzA(arow, kk * 2 + akh));

    const int tr = lane >> 2, c2 = (lane & 3) * 2;
    const int pq0 = ((int*)(sm + A_PQ))[w * 16 + tr];
    const int pq1 = ((int*)(sm + A_PQ))[w * 16 + tr + 8];
    const int brow = (lane & 7) + ((lane & 16) >> 1);
    const int bkh = (lane >> 3) & 1;
    const int vrow = lane & 15, vch = lane >> 4;

    float o[16][4];
#pragma unroll
    for (int j = 0; j < 16; j++)
#pragma unroll
        for (int r = 0; r < 4; r++) o[j][r] = 0.f;
    float mr0 = -1e30f, mr1 = -1e30f, lr0 = 0.f, lr1 = 0.f;

    auto issue = [&](int t) {
        const uint32_t st = sb + A_ST + (t & 1) * A_STG;
        const int k0 = t * ABK;
#pragma unroll
        for (int i = 0; i < 2; i++) {
            int idx = tid + i * 128;
            int row = idx >> 4, ch = idx & 15;
            size_t gk = (size_t)(k0 + row) * QKV_W + koff + ch * 8;
            size_t gv = (size_t)(k0 + row) * QKV_W + voff + ch * 8;
            uint32_t so = swzA(row, ch);
            cpasync16(st + A_KH + so, qkvh + gk);
            cpasync16(st + A_KL + so, qkvl + gk);
            cpasync16(st + A_VH + so, qkvh + gv);
            cpasync16(st + A_VL + so, qkvl + gv);
        }
        if (tid < ABK)
            cpasync4(sb + A_PK + (t & 1) * 64 + tid * 4, pos + k0 + tid);
        asm volatile("cp.async.commit_group;" ::: "memory");
    };

    issue(0);
    for (int t = 0; t < nt; t++) {
        if (t + 1 < nt) {
            issue(t + 1);
            asm volatile("cp.async.wait_group 1;" ::: "memory");
        } else {
            asm volatile("cp.async.wait_group 0;" ::: "memory");
        }
        __syncthreads();

        const uint32_t st = sb + A_ST + (t & 1) * A_STG;
        const int* pks = (const int*)(sm + A_PK + (t & 1) * 64);

        // ---- S (16 x 16) = Q K^T, 3-term bf16 ----
        float s4[2][4];
#pragma unroll
        for (int ng = 0; ng < 2; ng++)
#pragma unroll
            for (int r = 0; r < 4; r++) s4[ng][r] = 0.f;
#pragma unroll
        for (int kk = 0; kk < 8; kk++) {
            uint32_t kh4[4], kl4[4], ql4[4];
            ldsm4(kh4, st + A_KH + swzA(brow, kk * 2 + bkh));
            mma_bf16(s4[0], qh[kk], &kh4[0]);
            mma_bf16(s4[1], qh[kk], &kh4[2]);
            ldsm4(kl4, st + A_KL + swzA(brow, kk * 2 + bkh));
            mma_bf16(s4[0], qh[kk], &kl4[0]);
            mma_bf16(s4[1], qh[kk], &kl4[2]);
            ldsm4(ql4, sb + A_QL + swzA(arow, kk * 2 + akh));
            mma_bf16(s4[0], ql4, &kh4[0]);
            mma_bf16(s4[1], ql4, &kh4[2]);
        }

        // ---- bias + mask + online softmax (warp-local rows) ----
        float mx0 = -FLT_MAX, mx1 = -FLT_MAX;
#pragma unroll
        for (int ng = 0; ng < 2; ng++) {
            int pk0 = pks[ng * 8 + c2], pk1 = pks[ng * 8 + c2 + 1];
            int d00 = pq0 - pk0, d01 = pq0 - pk1;
            int d10 = pq1 - pk0, d11 = pq1 - pk1;
            float v00 = fmaf(nslope, tab[d00 < 0 ? 0 : d00], s4[ng][0]);
            float v01 = fmaf(nslope, tab[d01 < 0 ? 0 : d01], s4[ng][1]);
            float v10 = fmaf(nslope, tab[d10 < 0 ? 0 : d10], s4[ng][2]);
            float v11 = fmaf(nslope, tab[d11 < 0 ? 0 : d11], s4[ng][3]);
            s4[ng][0] = (d00 < 0) ? -FLT_MAX : v00;
            s4[ng][1] = (d01 < 0) ? -FLT_MAX : v01;
            s4[ng][2] = (d10 < 0) ? -FLT_MAX : v10;
            s4[ng][3] = (d11 < 0) ? -FLT_MAX : v11;
            mx0 = fmaxf(mx0, fmaxf(s4[ng][0], s4[ng][1]));
            mx1 = fmaxf(mx1, fmaxf(s4[ng][2], s4[ng][3]));
        }
        mx0 = fmaxf(mx0, __shfl_xor_sync(0xffffffffu, mx0, 1));
        mx0 = fmaxf(mx0, __shfl_xor_sync(0xffffffffu, mx0, 2));
        mx1 = fmaxf(mx1, __shfl_xor_sync(0xffffffffu, mx1, 1));
        mx1 = fmaxf(mx1, __shfl_xor_sync(0xffffffffu, mx1, 2));
        float mn0 = fmaxf(mr0, mx0), mn1 = fmaxf(mr1, mx1);
        float fac0 = __expf(mr0 - mn0), fac1 = __expf(mr1 - mn1);
        mr0 = mn0; mr1 = mn1;

        float sum0 = 0.f, sum1 = 0.f;
        uint32_t pa[4], pla[4];
#pragma unroll
        for (int ng = 0; ng < 2; ng++) {
            float p0 = __expf(s4[ng][0] - mn0);
            float p1 = __expf(s4[ng][1] - mn0);
            float p2 = __expf(s4[ng][2] - mn1);
            float p3 = __expf(s4[ng][3] - mn1);
            sum0 += p0 + p1;
            sum1 += p2 + p3;
            uint32_t hp01, lp01, hp23, lp23;
            split2(p0, p1, hp01, lp01);
            split2(p2, p3, hp23, lp23);
            pa[ng * 2]      = hp01;
            pa[ng * 2 + 1]  = hp23;
            pla[ng * 2]     = lp01;
            pla[ng * 2 + 1] = lp23;
        }
        sum0 += __shfl_xor_sync(0xffffffffu, sum0, 1);
        sum0 += __shfl_xor_sync(0xffffffffu, sum0, 2);
        sum1 += __shfl_xor_sync(0xffffffffu, sum1, 1);
        sum1 += __shfl_xor_sync(0xffffffffu, sum1, 2);
        lr0 = lr0 * fac0 + sum0;
        lr1 = lr1 * fac1 + sum1;
#pragma unroll
        for (int j = 0; j < 16; j++) {
            o[j][0] *= fac0; o[j][1] *= fac0;
            o[j][2] *= fac1; o[j][3] *= fac1;
        }

        // ---- O (16 x 128) += P V, 3-term ----
#pragma unroll
        for (int j2 = 0; j2 < 8; j2++) {
            const uint32_t vaddr = swzA(vrow, j2 * 2 + vch);
            uint32_t vh4[4], vl4[4];
            ldsm4t(vh4, st + A_VH + vaddr);
            mma_bf16(o[2 * j2],     pa,  &vh4[0]);
            mma_bf16(o[2 * j2 + 1], pa,  &vh4[2]);
            mma_bf16(o[2 * j2],     pla, &vh4[0]);
            mma_bf16(o[2 * j2 + 1], pla, &vh4[2]);
            ldsm4t(vl4, st + A_VL + vaddr);
            mma_bf16(o[2 * j2],     pa,  &vl4[0]);
            mma_bf16(o[2 * j2 + 1], pa,  &vl4[2]);
        }
        __syncthreads();
    }

    // ---- epilogue: normalize, hi/lo split, store ----
    float inv0 = 1.f / lr0, inv1 = 1.f / lr1;
    int row0 = q0 + w * 16 + tr, row1 = row0 + 8;
#pragma unroll
    for (int j = 0; j < 16; j++) {
        int col = qoff + j * 8 + c2;
        uint32_t hp, lp;
        split2(o[j][0] * inv0, o[j][1] * inv0, hp, lp);
        *(uint32_t*)(oh + (size_t)row0 * Q_SIZE + col) = hp;
        *(uint32_t*)(ol + (size_t)row0 * Q_SIZE + col) = lp;
        split2(o[j][2] * inv1, o[j][3] * inv1, hp, lp);
        *(uint32_t*)(oh + (size_t)row1 * Q_SIZE + col) = hp;
        *(uint32_t*)(ol + (size_t)row1 * Q_SIZE + col) = lp;
    }
}

// ---------------------------------------------------------------------------
extern "C" void kernel_launch(void* const* d_in, const int* in_sizes, int n_in,
                              void* d_out, int out_size)
{
    (void)in_sizes; (void)n_in; (void)out_size;
    const int*   pos  = (const int*)d_in[0];
    const float* hs   = (const float*)d_in[1];
    const float* wqkv = (const float*)d_in[2];
    const float* wo   = (const float*)d_in[3];
    float* out = (float*)d_out;

    __nv_bfloat16 *hs_h, *hs_l, *wq_h, *wq_l, *wo_h, *wo_l;
    __nv_bfloat16 *qk_h, *qk_l, *at_h, *at_l;
    cudaGetSymbolAddress((void**)&hs_h, g_hs_h);
    cudaGetSymbolAddress((void**)&hs_l, g_hs_l);
    cudaGetSymbolAddress((void**)&wq_h, g_wqkv_h);
    cudaGetSymbolAddress((void**)&wq_l, g_wqkv_l);
    cudaGetSymbolAddress((void**)&wo_h, g_wo_h);
    cudaGetSymbolAddress((void**)&wo_l, g_wo_l);
    cudaGetSymbolAddress((void**)&qk_h, g_qkv_h);
    cudaGetSymbolAddress((void**)&qk_l, g_qkv_l);
    cudaGetSymbolAddress((void**)&at_h, g_at_h);
    cudaGetSymbolAddress((void**)&at_l, g_at_l);

    cudaFuncSetAttribute(gemm_mma_t<0>,
                         cudaFuncAttributeMaxDynamicSharedMemorySize, GEMM_SMEM);
    cudaFuncSetAttribute(gemm_mma_t<1>,
                         cudaFuncAttributeMaxDynamicSharedMemorySize, GEMM_SMEM);
    cudaFuncSetAttribute(attn_tc,
                         cudaFuncAttributeMaxDynamicSharedMemorySize, A_SMEM);

    // 0) split inputs to bf16 hi/lo
    split_kernel<<<(S_LEN * HID) / 1024, 256>>>(hs, hs_h, hs_l, S_LEN * HID);
    split_kernel<<<(QKV_W * HID) / 1024, 256>>>(wqkv, wq_h, wq_l, QKV_W * HID);
    split_kernel<<<(HID * HID) / 1024, 256>>>(wo, wo_h, wo_l, HID * HID);

    // 1) QKV projection (HMMA) -> hi/lo bf16, Q pre-scaled
    gemm_mma_t<1><<<dim3(QKV_W / 128, S_LEN / 128), 256, GEMM_SMEM>>>(
        hs_h, hs_l, wq_h, wq_l, nullptr, qk_h, qk_l, S_LEN, QKV_W, HID);

    // 2) tensor-core attention -> hi/lo bf16
    attn_tc<<<dim3(S_LEN / ABQ, NH), 128, A_SMEM>>>(qk_h, qk_l, pos,
                                                    at_h, at_l);

    // 3) O-projection (HMMA) -> fp32 out
    gemm_mma_t<0><<<dim3(HID / 128, S_LEN / 128), 256, GEMM_SMEM>>>(
        at_h, at_l, wo_h, wo_l, out, nullptr, nullptr, S_LEN, HID, HID);
}

// round 14
// speedup vs baseline: 1.8736x; 1.3677x over previous
#include <cuda_runtime.h>
#include <cuda_bf16.h>
#include <cuda_fp16.h>
#include <math.h>
#include <float.h>
#include <stdint.h>

#define S_LEN  2048
#define HID    4096
#define NH     32
#define HD     128
#define QKV_W  12288
#define Q_SIZE 4096
#define KV_SIZE 1024

// GEMM tile config: CTA 128x128, K chunk 32 (fp16), 2 stages, 2-term
#define CHK 32
#define A_OFF  0
#define BH_OFF 8192
#define BL_OFF 16384
#define STAGE  24576
#define GEMM_SMEM (2 * STAGE)

// Attention (tensor) config: 128 threads, BQ=64 q rows, BK=16 keys (R13)
#define ABQ 64
#define ABK 16
#define A_QH   0
#define A_QL   16384
#define A_ST   32768          // 2 stages x 16KB
#define A_STG  16384
#define A_KH   0
#define A_KL   4096
#define A_VH   8192
#define A_VL   12288
#define A_TAB  65536
#define A_PQ   73728
#define A_PK   73984
#define A_SMEM 74112

// ---------------------------------------------------------------------------
// Scratch (device globals: allocation-free rule)
// ---------------------------------------------------------------------------
__device__ __align__(256) __half g_hs_f[(size_t)S_LEN * HID];
__device__ __align__(256) __half g_wqkv_h[(size_t)QKV_W * HID];
__device__ __align__(256) __half g_wqkv_l[(size_t)QKV_W * HID];
__device__ __align__(256) __half g_wo_h[(size_t)HID * HID];
__device__ __align__(256) __half g_wo_l[(size_t)HID * HID];
__device__ __align__(256) __nv_bfloat16 g_qkv_h[(size_t)S_LEN * QKV_W];
__device__ __align__(256) __nv_bfloat16 g_qkv_l[(size_t)S_LEN * QKV_W];
__device__ __align__(256) __half g_at_f[(size_t)S_LEN * Q_SIZE];

// ---------------------------------------------------------------------------
// PTX helpers (plain sm_80-era PTX)
// ---------------------------------------------------------------------------
__device__ __forceinline__ uint32_t smem_u32(const void* p) {
    uint32_t a;
    asm("{ .reg .u64 t; cvta.to.shared.u64 t, %1; cvt.u32.u64 %0, t; }"
        : "=r"(a) : "l"(p));
    return a;
}
__device__ __forceinline__ void cpasync16(uint32_t dst, const void* src) {
    asm volatile("cp.async.cg.shared.global [%0], [%1], 16;"
                 :: "r"(dst), "l"(src) : "memory");
}
__device__ __forceinline__ void cpasync4(uint32_t dst, const void* src) {
    asm volatile("cp.async.ca.shared.global [%0], [%1], 4;"
                 :: "r"(dst), "l"(src) : "memory");
}
__device__ __forceinline__ void ldsm4(uint32_t* r, uint32_t addr) {
    asm volatile("ldmatrix.sync.aligned.m8n8.x4.shared.b16 {%0,%1,%2,%3}, [%4];"
                 : "=r"(r[0]), "=r"(r[1]), "=r"(r[2]), "=r"(r[3]) : "r"(addr));
}
__device__ __forceinline__ void ldsm4t(uint32_t* r, uint32_t addr) {
    asm volatile("ldmatrix.sync.aligned.m8n8.x4.trans.shared.b16 {%0,%1,%2,%3}, [%4];"
                 : "=r"(r[0]), "=r"(r[1]), "=r"(r[2]), "=r"(r[3]) : "r"(addr));
}
__device__ __forceinline__ void mma_bf16(float* d, const uint32_t* a,
                                         const uint32_t* b) {
    asm volatile(
        "mma.sync.aligned.m16n8k16.row.col.f32.bf16.bf16.f32 "
        "{%0,%1,%2,%3}, {%4,%5,%6,%7}, {%8,%9}, {%0,%1,%2,%3};"
        : "+f"(d[0]), "+f"(d[1]), "+f"(d[2]), "+f"(d[3])
        : "r"(a[0]), "r"(a[1]), "r"(a[2]), "r"(a[3]), "r"(b[0]), "r"(b[1]));
}
__device__ __forceinline__ void mma_fp16(float* d, const uint32_t* a,
                                         const uint32_t* b) {
    asm volatile(
        "mma.sync.aligned.m16n8k16.row.col.f32.f16.f16.f32 "
        "{%0,%1,%2,%3}, {%4,%5,%6,%7}, {%8,%9}, {%0,%1,%2,%3};"
        : "+f"(d[0]), "+f"(d[1]), "+f"(d[2]), "+f"(d[3])
        : "r"(a[0]), "r"(a[1]), "r"(a[2]), "r"(a[3]), "r"(b[0]), "r"(b[1]));
}
__device__ __forceinline__ uint32_t swz(int row, int seg) {       // 64B rows
    return row * 64 + ((seg ^ ((row >> 1) & 3)) << 4);
}
__device__ __forceinline__ uint32_t swzA(int row, int chunk) {    // 256B rows
    return row * 256 + ((chunk ^ (row & 7)) << 4);
}
// bf16 pair split (for QKV epilogue / attention P, unchanged numerics)
__device__ __forceinline__ void split2(float v0, float v1,
                                       uint32_t& hp, uint32_t& lp) {
    uint32_t u0 = __float_as_uint(v0) & 0xFFFF0000u;
    uint32_t u1 = __float_as_uint(v1) & 0xFFFF0000u;
    hp = (u0 >> 16) | u1;
    float r0 = v0 - __uint_as_float(u0);
    float r1 = v1 - __uint_as_float(u1);
    asm("cvt.rn.bf16x2.f32 %0, %1, %2;" : "=r"(lp) : "f"(r1), "f"(r0));
}
// fp16 pair split (hi = rn(x), lo = rn(x - hi))
__device__ __forceinline__ void split2h(float v0, float v1,
                                        uint32_t& hp, uint32_t& lp) {
    __half h0 = __float2half_rn(v0);
    __half h1 = __float2half_rn(v1);
    asm("mov.b32 %0, {%1, %2};" : "=r"(hp)
        : "h"(__half_as_ushort(h0)), "h"(__half_as_ushort(h1)));
    float r0 = v0 - __half2float(h0);
    float r1 = v1 - __half2float(h1);
    asm("cvt.rn.f16x2.f32 %0, %1, %2;" : "=r"(lp) : "f"(r1), "f"(r0));
}
__device__ __forceinline__ uint32_t pack_h2(float v0, float v1) {
    uint32_t p;
    asm("cvt.rn.f16x2.f32 %0, %1, %2;" : "=r"(p) : "f"(v1), "f"(v0));
    return p;
}

// ---------------------------------------------------------------------------
// fp32 -> fp16 hi/lo split
// ---------------------------------------------------------------------------
__global__ __launch_bounds__(256) void splith_kernel(
    const float* __restrict__ x, __half* __restrict__ hi,
    __half* __restrict__ lo, int n)
{
    int i = (blockIdx.x * 256 + threadIdx.x) * 4;
    if (i >= n) return;
    float4 v = *(const float4*)(x + i);
    uint32_t h01, l01, h23, l23;
    split2h(v.x, v.y, h01, l01);
    split2h(v.z, v.w, h23, l23);
    *(uint2*)(hi + i) = make_uint2(h01, h23);
    *(uint2*)(lo + i) = make_uint2(l01, l23);
}
// fp32 -> fp16 single
__global__ __launch_bounds__(256) void convh_kernel(
    const float* __restrict__ x, __half* __restrict__ f, int n)
{
    int i = (blockIdx.x * 256 + threadIdx.x) * 4;
    if (i >= n) return;
    float4 v = *(const float4*)(x + i);
    *(uint2*)(f + i) = make_uint2(pack_h2(v.x, v.y), pack_h2(v.z, v.w));
}

// ---------------------------------------------------------------------------
// HMMA 2-term fp16 GEMM NT: C = A_fp16 * (Bh + Bl)^T.
// MODE 0: fp32 out. MODE 1: hi/lo bf16 out, cols < Q_SIZE scaled by 128^-0.5.
// Structure identical to proven R12 body, minus the third term and A-lo.
// ---------------------------------------------------------------------------
template<int MODE>
__global__ __launch_bounds__(256, 2) void gemm_h2(
    const __half* __restrict__ A,
    const __half* __restrict__ Bh, const __half* __restrict__ Bl,
    float* __restrict__ C, __nv_bfloat16* __restrict__ Ch,
    __nv_bfloat16* __restrict__ Cl, int M, int N, int K)
{
    extern __shared__ __align__(128) char smem_g[];
    const uint32_t sb = smem_u32(smem_g);
    const int tid  = threadIdx.x;
    const int lane = tid & 31, warp = tid >> 5;
    const int wm = warp >> 1, wn = warp & 1;
    const int m0 = blockIdx.y << 7, n0 = blockIdx.x << 7;
    const int NC = K / CHK;

    const int a_row = lane & 15;
    const int a_kh  = lane >> 4;
    const int b_row = (lane & 7) + ((lane & 16) >> 1);
    const int b_kh  = (lane >> 3) & 1;

    float acc[2][8][4];
#pragma unroll
    for (int mt = 0; mt < 2; mt++)
#pragma unroll
        for (int ng = 0; ng < 8; ng++)
#pragma unroll
            for (int r = 0; r < 4; r++) acc[mt][ng][r] = 0.f;

    auto load_chunk = [&](int c, int s) {
        const uint32_t st = sb + s * STAGE;
        const int k0 = c * CHK;
#pragma unroll
        for (int i = 0; i < 2; i++) {
            int idx = tid + i * 256;
            int row = idx >> 2, seg = idx & 3;
            uint32_t so = swz(row, seg);
            size_t ga = (size_t)(m0 + row) * K + k0 + seg * 8;
            size_t gb = (size_t)(n0 + row) * K + k0 + seg * 8;
            cpasync16(st + A_OFF + so, A + ga);
            cpasync16(st + BH_OFF + so, Bh + gb);
            cpasync16(st + BL_OFF + so, Bl + gb);
        }
        asm volatile("cp.async.commit_group;" ::: "memory");
    };

    load_chunk(0, 0);
    if (NC > 1) load_chunk(1, 1);

    for (int c = 0; c < NC; c++) {
        if (c + 1 < NC)
            asm volatile("cp.async.wait_group 1;" ::: "memory");
        else
            asm volatile("cp.async.wait_group 0;" ::: "memory");
        __syncthreads();

        const uint32_t st = sb + (c & 1) * STAGE;
#pragma unroll
        for (int kk = 0; kk < 2; kk++) {
            uint32_t ah[2][4], bh[4][4], bl[4][4];
#pragma unroll
            for (int mt = 0; mt < 2; mt++) {
                int r = wm * 32 + mt * 16 + a_row;
                ldsm4(ah[mt], st + A_OFF + swz(r, kk * 2 + a_kh));
            }
#pragma unroll
            for (int g = 0; g < 4; g++) {
                int r = wn * 64 + g * 16 + b_row;
                ldsm4(bh[g], st + BH_OFF + swz(r, kk * 2 + b_kh));
            }
#pragma unroll
            for (int mt = 0; mt < 2; mt++)
#pragma unroll
                for (int ng = 0; ng < 8; ng++)
                    mma_fp16(acc[mt][ng], ah[mt], &bh[ng >> 1][(ng & 1) * 2]);
#pragma unroll
            for (int g = 0; g < 4; g++) {
                int r = wn * 64 + g * 16 + b_row;
                ldsm4(bl[g], st + BL_OFF + swz(r, kk * 2 + b_kh));
            }
#pragma unroll
            for (int mt = 0; mt < 2; mt++)
#pragma unroll
                for (int ng = 0; ng < 8; ng++)
                    mma_fp16(acc[mt][ng], ah[mt], &bl[ng >> 1][(ng & 1) * 2]);
        }
        __syncthreads();
        if (c + 2 < NC) load_chunk(c + 2, c & 1);
    }

    const int tr = lane >> 2, tc = (lane & 3) * 2;
    const float qsc = 0.08838834764831844f;
#pragma unroll
    for (int mt = 0; mt < 2; mt++) {
        int row = m0 + wm * 32 + mt * 16 + tr;
#pragma unroll
        for (int ng = 0; ng < 8; ng++) {
            int col = n0 + wn * 64 + ng * 8 + tc;
            if (MODE == 0) {
                *(float2*)(C + (size_t)row * N + col) =
                    make_float2(acc[mt][ng][0], acc[mt][ng][1]);
                *(float2*)(C + (size_t)(row + 8) * N + col) =
                    make_float2(acc[mt][ng][2], acc[mt][ng][3]);
            } else {
                float sc = (col < Q_SIZE) ? qsc : 1.f;
                uint32_t hp, lp;
                split2(acc[mt][ng][0] * sc, acc[mt][ng][1] * sc, hp, lp);
                *(uint32_t*)(Ch + (size_t)row * N + col) = hp;
                *(uint32_t*)(Cl + (size_t)row * N + col) = lp;
                split2(acc[mt][ng][2] * sc, acc[mt][ng][3] * sc, hp, lp);
                *(uint32_t*)(Ch + (size_t)(row + 8) * N + col) = hp;
                *(uint32_t*)(Cl + (size_t)(row + 8) * N + col) = lp;
            }
        }
    }
}

// ---------------------------------------------------------------------------
// Tensor-core flash attention v3 (R13, proven): 128 threads / 4 warps,
// BQ=64, BK=16, bf16 3-term, 3 CTAs/SM. Epilogue now emits single fp16.
// ---------------------------------------------------------------------------
__global__ __launch_bounds__(128, 3) void attn_tc(
    const __nv_bfloat16* __restrict__ qkvh,
    const __nv_bfloat16* __restrict__ qkvl,
    const int* __restrict__ pos,
    __half* __restrict__ of)
{
    extern __shared__ __align__(1024) char sm[];
    const uint32_t sb = smem_u32(sm);
    const int tid = threadIdx.x, lane = tid & 31, w = tid >> 5;
    const int qt = gridDim.x - 1 - blockIdx.x;
    const int h = blockIdx.y, g = h >> 2;
    const int q0 = qt * ABQ;
    const float nslope = -exp2f(-0.25f * (float)(h + 1));
    const int qoff = h * HD;
    const int koff = Q_SIZE + g * HD;
    const int voff = Q_SIZE + KV_SIZE + g * HD;
    const int nt = 4 * (qt + 1);

    float* tab = (float*)(sm + A_TAB);
    for (int i = tid; i < 2048; i += 128) tab[i] = sqrtf((float)i);
    if (tid < ABQ) ((int*)(sm + A_PQ))[tid] = pos[q0 + tid];

#pragma unroll
    for (int i = 0; i < 8; i++) {
        int idx = tid + i * 128;
        int row = idx >> 4, ch = idx & 15;
        size_t go = (size_t)(q0 + row) * QKV_W + qoff + ch * 8;
        cpasync16(sb + A_QH + swzA(row, ch), qkvh + go);
        cpasync16(sb + A_QL + swzA(row, ch), qkvl + go);
    }
    asm volatile("cp.async.commit_group;" ::: "memory");
    asm volatile("cp.async.wait_group 0;" ::: "memory");
    __syncthreads();

    const int arow = w * 16 + (lane & 15);
    const int akh = lane >> 4;
    uint32_t qh[8][4];
#pragma unroll
    for (int kk = 0; kk < 8; kk++)
        ldsm4(qh[kk], sb + A_QH + swzA(arow, kk * 2 + akh));

    const int tr = lane >> 2, c2 = (lane & 3) * 2;
    const int pq0 = ((int*)(sm + A_PQ))[w * 16 + tr];
    const int pq1 = ((int*)(sm + A_PQ))[w * 16 + tr + 8];
    const int brow = (lane & 7) + ((lane & 16) >> 1);
    const int bkh = (lane >> 3) & 1;
    const int vrow = lane & 15, vch = lane >> 4;

    float o[16][4];
#pragma unroll
    for (int j = 0; j < 16; j++)
#pragma unroll
        for (int r = 0; r < 4; r++) o[j][r] = 0.f;
    float mr0 = -1e30f, mr1 = -1e30f, lr0 = 0.f, lr1 = 0.f;

    auto issue = [&](int t) {
        const uint32_t st = sb + A_ST + (t & 1) * A_STG;
        const int k0 = t * ABK;
#pragma unroll
        for (int i = 0; i < 2; i++) {
            int idx = tid + i * 128;
            int row = idx >> 4, ch = idx & 15;
            size_t gk = (size_t)(k0 + row) * QKV_W + koff + ch * 8;
            size_t gv = (size_t)(k0 + row) * QKV_W + voff + ch * 8;
            uint32_t so = swzA(row, ch);
            cpasync16(st + A_KH + so, qkvh + gk);
            cpasync16(st + A_KL + so, qkvl + gk);
            cpasync16(st + A_VH + so, qkvh + gv);
            cpasync16(st + A_VL + so, qkvl + gv);
        }
        if (tid < ABK)
            cpasync4(sb + A_PK + (t & 1) * 64 + tid * 4, pos + k0 + tid);
        asm volatile("cp.async.commit_group;" ::: "memory");
    };

    issue(0);
    for (int t = 0; t < nt; t++) {
        if (t + 1 < nt) {
            issue(t + 1);
            asm volatile("cp.async.wait_group 1;" ::: "memory");
        } else {
            asm volatile("cp.async.wait_group 0;" ::: "memory");
        }
        __syncthreads();

        const uint32_t st = sb + A_ST + (t & 1) * A_STG;
        const int* pks = (const int*)(sm + A_PK + (t & 1) * 64);

        float s4[2][4];
#pragma unroll
        for (int ng = 0; ng < 2; ng++)
#pragma unroll
            for (int r = 0; r < 4; r++) s4[ng][r] = 0.f;
#pragma unroll
        for (int kk = 0; kk < 8; kk++) {
            uint32_t kh4[4], kl4[4], ql4[4];
            ldsm4(kh4, st + A_KH + swzA(brow, kk * 2 + bkh));
            mma_bf16(s4[0], qh[kk], &kh4[0]);
            mma_bf16(s4[1], qh[kk], &kh4[2]);
            ldsm4(kl4, st + A_KL + swzA(brow, kk * 2 + bkh));
            mma_bf16(s4[0], qh[kk], &kl4[0]);
            mma_bf16(s4[1], qh[kk], &kl4[2]);
            ldsm4(ql4, sb + A_QL + swzA(arow, kk * 2 + akh));
            mma_bf16(s4[0], ql4, &kh4[0]);
            mma_bf16(s4[1], ql4, &kh4[2]);
        }

        float mx0 = -FLT_MAX, mx1 = -FLT_MAX;
#pragma unroll
        for (int ng = 0; ng < 2; ng++) {
            int pk0 = pks[ng * 8 + c2], pk1 = pks[ng * 8 + c2 + 1];
            int d00 = pq0 - pk0, d01 = pq0 - pk1;
            int d10 = pq1 - pk0, d11 = pq1 - pk1;
            float v00 = fmaf(nslope, tab[d00 < 0 ? 0 : d00], s4[ng][0]);
            float v01 = fmaf(nslope, tab[d01 < 0 ? 0 : d01], s4[ng][1]);
            float v10 = fmaf(nslope, tab[d10 < 0 ? 0 : d10], s4[ng][2]);
            float v11 = fmaf(nslope, tab[d11 < 0 ? 0 : d11], s4[ng][3]);
            s4[ng][0] = (d00 < 0) ? -FLT_MAX : v00;
            s4[ng][1] = (d01 < 0) ? -FLT_MAX : v01;
            s4[ng][2] = (d10 < 0) ? -FLT_MAX : v10;
            s4[ng][3] = (d11 < 0) ? -FLT_MAX : v11;
            mx0 = fmaxf(mx0, fmaxf(s4[ng][0], s4[ng][1]));
            mx1 = fmaxf(mx1, fmaxf(s4[ng][2], s4[ng][3]));
        }
        mx0 = fmaxf(mx0, __shfl_xor_sync(0xffffffffu, mx0, 1));
        mx0 = fmaxf(mx0, __shfl_xor_sync(0xffffffffu, mx0, 2));
        mx1 = fmaxf(mx1, __shfl_xor_sync(0xffffffffu, mx1, 1));
        mx1 = fmaxf(mx1, __shfl_xor_sync(0xffffffffu, mx1, 2));
        float mn0 = fmaxf(mr0, mx0), mn1 = fmaxf(mr1, mx1);
        float fac0 = __expf(mr0 - mn0), fac1 = __expf(mr1 - mn1);
        mr0 = mn0; mr1 = mn1;

        float sum0 = 0.f, sum1 = 0.f;
        uint32_t pa[4], pla[4];
#pragma unroll
        for (int ng = 0; ng < 2; ng++) {
            float p0 = __expf(s4[ng][0] - mn0);
            float p1 = __expf(s4[ng][1] - mn0);
            float p2 = __expf(s4[ng][2] - mn1);
            float p3 = __expf(s4[ng][3] - mn1);
            sum0 += p0 + p1;
            sum1 += p2 + p3;
            uint32_t hp01, lp01, hp23, lp23;
            split2(p0, p1, hp01, lp01);
            split2(p2, p3, hp23, lp23);
            pa[ng * 2]      = hp01;
            pa[ng * 2 + 1]  = hp23;
            pla[ng * 2]     = lp01;
            pla[ng * 2 + 1] = lp23;
        }
        sum0 += __shfl_xor_sync(0xffffffffu, sum0, 1);
        sum0 += __shfl_xor_sync(0xffffffffu, sum0, 2);
        sum1 += __shfl_xor_sync(0xffffffffu, sum1, 1);
        sum1 += __shfl_xor_sync(0xffffffffu, sum1, 2);
        lr0 = lr0 * fac0 + sum0;
        lr1 = lr1 * fac1 + sum1;
#pragma unroll
        for (int j = 0; j < 16; j++) {
            o[j][0] *= fac0; o[j][1] *= fac0;
            o[j][2] *= fac1; o[j][3] *= fac1;
        }

#pragma unroll
        for (int j2 = 0; j2 < 8; j2++) {
            const uint32_t vaddr = swzA(vrow, j2 * 2 + vch);
            uint32_t vh4[4], vl4[4];
            ldsm4t(vh4, st + A_VH + vaddr);
            mma_bf16(o[2 * j2],     pa,  &vh4[0]);
            mma_bf16(o[2 * j2 + 1], pa,  &vh4[2]);
            mma_bf16(o[2 * j2],     pla, &vh4[0]);
            mma_bf16(o[2 * j2 + 1], pla, &vh4[2]);
            ldsm4t(vl4, st + A_VL + vaddr);
            mma_bf16(o[2 * j2],     pa,  &vl4[0]);
            mma_bf16(o[2 * j2 + 1], pa,  &vl4[2]);
        }
        __syncthreads();
    }

    // epilogue: normalize, emit SINGLE fp16 (O-proj A operand)
    float inv0 = 1.f / lr0, inv1 = 1.f / lr1;
    int row0 = q0 + w * 16 + tr, row1 = row0 + 8;
#pragma unroll
    for (int j = 0; j < 16; j++) {
        int col = qoff + j * 8 + c2;
        *(uint32_t*)(of + (size_t)row0 * Q_SIZE + col) =
            pack_h2(o[j][0] * inv0, o[j][1] * inv0);
        *(uint32_t*)(of + (size_t)row1 * Q_SIZE + col) =
            pack_h2(o[j][2] * inv1, o[j][3] * inv1);
    }
}

// ---------------------------------------------------------------------------
extern "C" void kernel_launch(void* const* d_in, const int* in_sizes, int n_in,
                              void* d_out, int out_size)
{
    (void)in_sizes; (void)n_in; (void)out_size;
    const int*   pos  = (const int*)d_in[0];
    const float* hs   = (const float*)d_in[1];
    const float* wqkv = (const float*)d_in[2];
    const float* wo   = (const float*)d_in[3];
    float* out = (float*)d_out;

    __half *hs_f, *wq_h, *wq_l, *wo_h, *wo_l, *at_f;
    __nv_bfloat16 *qk_h, *qk_l;
    cudaGetSymbolAddress((void**)&hs_f, g_hs_f);
    cudaGetSymbolAddress((void**)&wq_h, g_wqkv_h);
    cudaGetSymbolAddress((void**)&wq_l, g_wqkv_l);
    cudaGetSymbolAddress((void**)&wo_h, g_wo_h);
    cudaGetSymbolAddress((void**)&wo_l, g_wo_l);
    cudaGetSymbolAddress((void**)&qk_h, g_qkv_h);
    cudaGetSymbolAddress((void**)&qk_l, g_qkv_l);
    cudaGetSymbolAddress((void**)&at_f, g_at_f);

    cudaFuncSetAttribute(gemm_h2<0>,
                         cudaFuncAttributeMaxDynamicSharedMemorySize, GEMM_SMEM);
    cudaFuncSetAttribute(gemm_h2<1>,
                         cudaFuncAttributeMaxDynamicSharedMemorySize, GEMM_SMEM);
    cudaFuncSetAttribute(attn_tc,
                         cudaFuncAttributeMaxDynamicSharedMemorySize, A_SMEM);

    // 0) convert/split inputs to fp16
    convh_kernel<<<(S_LEN * HID) / 1024, 256>>>(hs, hs_f, S_LEN * HID);
    splith_kernel<<<(QKV_W * HID) / 1024, 256>>>(wqkv, wq_h, wq_l, QKV_W * HID);
    splith_kernel<<<(HID * HID) / 1024, 256>>>(wo, wo_h, wo_l, HID * HID);

    // 1) QKV projection (fp16 2-term) -> hi/lo bf16, Q pre-scaled
    gemm_h2<1><<<dim3(QKV_W / 128, S_LEN / 128), 256, GEMM_SMEM>>>(
        hs_f, wq_h, wq_l, nullptr, qk_h, qk_l, S_LEN, QKV_W, HID);

    // 2) tensor-core attention (R13 core) -> single fp16
    attn_tc<<<dim3(S_LEN / ABQ, NH), 128, A_SMEM>>>(qk_h, qk_l, pos, at_f);

    // 3) O-projection (fp16 2-term) -> fp32 out
    gemm_h2<0><<<dim3(HID / 128, S_LEN / 128), 256, GEMM_SMEM>>>(
        at_f, wo_h, wo_l, out, nullptr, nullptr, S_LEN, HID, HID);
}

// round 15
// speedup vs baseline: 2.0410x; 1.0894x over previous
#include <cuda_runtime.h>
#include <cuda_bf16.h>
#include <cuda_fp16.h>
#include <math.h>
#include <float.h>
#include <stdint.h>

#define S_LEN  2048
#define HID    4096
#define NH     32
#define HD     128
#define QKV_W  12288
#define Q_SIZE 4096
#define KV_SIZE 1024

// GEMM tile config: CTA 128x128, K chunk 32 (fp16), 3 stages, 2-term
#define CHK 32
#define A_OFF  0
#define BH_OFF 8192
#define BL_OFF 16384
#define STAGE  24576
#define GEMM_SMEM (3 * STAGE)

// Attention (tensor) config: 128 threads, BQ=64 q rows, BK=16 keys (R13)
#define ABQ 64
#define ABK 16
#define A_QH   0
#define A_QL   16384
#define A_ST   32768          // 2 stages x 16KB
#define A_STG  16384
#define A_KH   0
#define A_KL   4096
#define A_VH   8192
#define A_VL   12288
#define A_TAB  65536
#define A_PQ   73728
#define A_PK   73984
#define A_SMEM 74112

// ---------------------------------------------------------------------------
// Scratch (device globals: allocation-free rule)
// ---------------------------------------------------------------------------
__device__ __align__(256) __half g_hs_f[(size_t)S_LEN * HID];
__device__ __align__(256) __half g_wqkv_h[(size_t)QKV_W * HID];
__device__ __align__(256) __half g_wqkv_l[(size_t)QKV_W * HID];
__device__ __align__(256) __half g_wo_h[(size_t)HID * HID];
__device__ __align__(256) __half g_wo_l[(size_t)HID * HID];
__device__ __align__(256) __nv_bfloat16 g_qkv_h[(size_t)S_LEN * QKV_W];
__device__ __align__(256) __nv_bfloat16 g_qkv_l[(size_t)S_LEN * QKV_W];
__device__ __align__(256) __half g_at_f[(size_t)S_LEN * Q_SIZE];

// ---------------------------------------------------------------------------
// PTX helpers (plain sm_80-era PTX)
// ---------------------------------------------------------------------------
__device__ __forceinline__ uint32_t smem_u32(const void* p) {
    uint32_t a;
    asm("{ .reg .u64 t; cvta.to.shared.u64 t, %1; cvt.u32.u64 %0, t; }"
        : "=r"(a) : "l"(p));
    return a;
}
__device__ __forceinline__ void cpasync16(uint32_t dst, const void* src) {
    asm volatile("cp.async.cg.shared.global [%0], [%1], 16;"
                 :: "r"(dst), "l"(src) : "memory");
}
__device__ __forceinline__ void cpasync4(uint32_t dst, const void* src) {
    asm volatile("cp.async.ca.shared.global [%0], [%1], 4;"
                 :: "r"(dst), "l"(src) : "memory");
}
__device__ __forceinline__ void ldsm4(uint32_t* r, uint32_t addr) {
    asm volatile("ldmatrix.sync.aligned.m8n8.x4.shared.b16 {%0,%1,%2,%3}, [%4];"
                 : "=r"(r[0]), "=r"(r[1]), "=r"(r[2]), "=r"(r[3]) : "r"(addr));
}
__device__ __forceinline__ void ldsm4t(uint32_t* r, uint32_t addr) {
    asm volatile("ldmatrix.sync.aligned.m8n8.x4.trans.shared.b16 {%0,%1,%2,%3}, [%4];"
                 : "=r"(r[0]), "=r"(r[1]), "=r"(r[2]), "=r"(r[3]) : "r"(addr));
}
__device__ __forceinline__ void mma_bf16(float* d, const uint32_t* a,
                                         const uint32_t* b) {
    asm volatile(
        "mma.sync.aligned.m16n8k16.row.col.f32.bf16.bf16.f32 "
        "{%0,%1,%2,%3}, {%4,%5,%6,%7}, {%8,%9}, {%0,%1,%2,%3};"
        : "+f"(d[0]), "+f"(d[1]), "+f"(d[2]), "+f"(d[3])
        : "r"(a[0]), "r"(a[1]), "r"(a[2]), "r"(a[3]), "r"(b[0]), "r"(b[1]));
}
__device__ __forceinline__ void mma_fp16(float* d, const uint32_t* a,
                                         const uint32_t* b) {
    asm volatile(
        "mma.sync.aligned.m16n8k16.row.col.f32.f16.f16.f32 "
        "{%0,%1,%2,%3}, {%4,%5,%6,%7}, {%8,%9}, {%0,%1,%2,%3};"
        : "+f"(d[0]), "+f"(d[1]), "+f"(d[2]), "+f"(d[3])
        : "r"(a[0]), "r"(a[1]), "r"(a[2]), "r"(a[3]), "r"(b[0]), "r"(b[1]));
}
__device__ __forceinline__ uint32_t swz(int row, int seg) {       // 64B rows
    return row * 64 + ((seg ^ ((row >> 1) & 3)) << 4);
}
__device__ __forceinline__ uint32_t swzA(int row, int chunk) {    // 256B rows
    return row * 256 + ((chunk ^ (row & 7)) << 4);
}
// bf16 pair split (QKV epilogue / attention P)
__device__ __forceinline__ void split2(float v0, float v1,
                                       uint32_t& hp, uint32_t& lp) {
    uint32_t u0 = __float_as_uint(v0) & 0xFFFF0000u;
    uint32_t u1 = __float_as_uint(v1) & 0xFFFF0000u;
    hp = (u0 >> 16) | u1;
    float r0 = v0 - __uint_as_float(u0);
    float r1 = v1 - __uint_as_float(u1);
    asm("cvt.rn.bf16x2.f32 %0, %1, %2;" : "=r"(lp) : "f"(r1), "f"(r0));
}
// fp16 pair split
__device__ __forceinline__ void split2h(float v0, float v1,
                                        uint32_t& hp, uint32_t& lp) {
    __half h0 = __float2half_rn(v0);
    __half h1 = __float2half_rn(v1);
    asm("mov.b32 %0, {%1, %2};" : "=r"(hp)
        : "h"(__half_as_ushort(h0)), "h"(__half_as_ushort(h1)));
    float r0 = v0 - __half2float(h0);
    float r1 = v1 - __half2float(h1);
    asm("cvt.rn.f16x2.f32 %0, %1, %2;" : "=r"(lp) : "f"(r1), "f"(r0));
}
__device__ __forceinline__ uint32_t pack_h2(float v0, float v1) {
    uint32_t p;
    asm("cvt.rn.f16x2.f32 %0, %1, %2;" : "=r"(p) : "f"(v1), "f"(v0));
    return p;
}

// ---------------------------------------------------------------------------
__global__ __launch_bounds__(256) void splith_kernel(
    const float* __restrict__ x, __half* __restrict__ hi,
    __half* __restrict__ lo, int n)
{
    int i = (blockIdx.x * 256 + threadIdx.x) * 4;
    if (i >= n) return;
    float4 v = *(const float4*)(x + i);
    uint32_t h01, l01, h23, l23;
    split2h(v.x, v.y, h01, l01);
    split2h(v.z, v.w, h23, l23);
    *(uint2*)(hi + i) = make_uint2(h01, h23);
    *(uint2*)(lo + i) = make_uint2(l01, l23);
}
__global__ __launch_bounds__(256) void convh_kernel(
    const float* __restrict__ x, __half* __restrict__ f, int n)
{
    int i = (blockIdx.x * 256 + threadIdx.x) * 4;
    if (i >= n) return;
    float4 v = *(const float4*)(x + i);
    *(uint2*)(f + i) = make_uint2(pack_h2(v.x, v.y), pack_h2(v.z, v.w));
}

// ---------------------------------------------------------------------------
// HMMA 2-term fp16 GEMM NT: C = A_fp16 * (Bh + Bl)^T.
// 3-stage cp.async pipeline, ONE barrier per K-chunk (stage written by
// load(c+2) is the stage compute(c-1) read; the barrier at iteration c
// already ordered compute(c-1) before any writes issued at iteration c).
// MODE 0: fp32 out. MODE 1: hi/lo bf16 out, cols < Q_SIZE scaled by 128^-0.5.
// ---------------------------------------------------------------------------
template<int MODE>
__global__ __launch_bounds__(256, 2) void gemm_h2(
    const __half* __restrict__ A,
    const __half* __restrict__ Bh, const __half* __restrict__ Bl,
    float* __restrict__ C, __nv_bfloat16* __restrict__ Ch,
    __nv_bfloat16* __restrict__ Cl, int M, int N, int K)
{
    extern __shared__ __align__(128) char smem_g[];
    const uint32_t sb = smem_u32(smem_g);
    const int tid  = threadIdx.x;
    const int lane = tid & 31, warp = tid >> 5;
    const int wm = warp >> 1, wn = warp & 1;
    const int m0 = blockIdx.y << 7, n0 = blockIdx.x << 7;
    const int NC = K / CHK;

    const int a_row = lane & 15;
    const int a_kh  = lane >> 4;
    const int b_row = (lane & 7) + ((lane & 16) >> 1);
    const int b_kh  = (lane >> 3) & 1;

    float acc[2][8][4];
#pragma unroll
    for (int mt = 0; mt < 2; mt++)
#pragma unroll
        for (int ng = 0; ng < 8; ng++)
#pragma unroll
            for (int r = 0; r < 4; r++) acc[mt][ng][r] = 0.f;

    auto load_chunk = [&](int c, int s) {
        const uint32_t st = sb + s * STAGE;
        const int k0 = c * CHK;
#pragma unroll
        for (int i = 0; i < 2; i++) {
            int idx = tid + i * 256;
            int row = idx >> 2, seg = idx & 3;
            uint32_t so = swz(row, seg);
            size_t ga = (size_t)(m0 + row) * K + k0 + seg * 8;
            size_t gb = (size_t)(n0 + row) * K + k0 + seg * 8;
            cpasync16(st + A_OFF + so, A + ga);
            cpasync16(st + BH_OFF + so, Bh + gb);
            cpasync16(st + BL_OFF + so, Bl + gb);
        }
        asm volatile("cp.async.commit_group;" ::: "memory");
    };

    load_chunk(0, 0);
    load_chunk(1, 1);

    int s = 0, s2 = 2;
    for (int c = 0; c < NC; c++) {
        if (c + 1 < NC)
            asm volatile("cp.async.wait_group 1;" ::: "memory");
        else
            asm volatile("cp.async.wait_group 0;" ::: "memory");
        __syncthreads();

        const uint32_t st = sb + s * STAGE;
#pragma unroll
        for (int kk = 0; kk < 2; kk++) {
            uint32_t ah[2][4], bh[4][4], bl[4][4];
#pragma unroll
            for (int mt = 0; mt < 2; mt++) {
                int r = wm * 32 + mt * 16 + a_row;
                ldsm4(ah[mt], st + A_OFF + swz(r, kk * 2 + a_kh));
            }
#pragma unroll
            for (int g = 0; g < 4; g++) {
                int r = wn * 64 + g * 16 + b_row;
                ldsm4(bh[g], st + BH_OFF + swz(r, kk * 2 + b_kh));
            }
#pragma unroll
            for (int mt = 0; mt < 2; mt++)
#pragma unroll
                for (int ng = 0; ng < 8; ng++)
                    mma_fp16(acc[mt][ng], ah[mt], &bh[ng >> 1][(ng & 1) * 2]);
#pragma unroll
            for (int g = 0; g < 4; g++) {
                int r = wn * 64 + g * 16 + b_row;
                ldsm4(bl[g], st + BL_OFF + swz(r, kk * 2 + b_kh));
            }
#pragma unroll
            for (int mt = 0; mt < 2; mt++)
#pragma unroll
                for (int ng = 0; ng < 8; ng++)
                    mma_fp16(acc[mt][ng], ah[mt], &bl[ng >> 1][(ng & 1) * 2]);
        }
        // no second barrier: with 3 stages, the stage load(c+2) writes was
        // last read at compute(c-1), ordered by this iteration's barrier.
        if (c + 2 < NC) load_chunk(c + 2, s2);
        s  = (s  == 2) ? 0 : s + 1;
        s2 = (s2 == 2) ? 0 : s2 + 1;
    }

    const int tr = lane >> 2, tc = (lane & 3) * 2;
    const float qsc = 0.08838834764831844f;
#pragma unroll
    for (int mt = 0; mt < 2; mt++) {
        int row = m0 + wm * 32 + mt * 16 + tr;
#pragma unroll
        for (int ng = 0; ng < 8; ng++) {
            int col = n0 + wn * 64 + ng * 8 + tc;
            if (MODE == 0) {
                *(float2*)(C + (size_t)row * N + col) =
                    make_float2(acc[mt][ng][0], acc[mt][ng][1]);
                *(float2*)(C + (size_t)(row + 8) * N + col) =
                    make_float2(acc[mt][ng][2], acc[mt][ng][3]);
            } else {
                float sc = (col < Q_SIZE) ? qsc : 1.f;
                uint32_t hp, lp;
                split2(acc[mt][ng][0] * sc, acc[mt][ng][1] * sc, hp, lp);
                *(uint32_t*)(Ch + (size_t)row * N + col) = hp;
                *(uint32_t*)(Cl + (size_t)row * N + col) = lp;
                split2(acc[mt][ng][2] * sc, acc[mt][ng][3] * sc, hp, lp);
                *(uint32_t*)(Ch + (size_t)(row + 8) * N + col) = hp;
                *(uint32_t*)(Cl + (size_t)(row + 8) * N + col) = lp;
            }
        }
    }
}

// ---------------------------------------------------------------------------
// Tensor-core flash attention v3 (R13/R14, proven): 128 threads / 4 warps,
// BQ=64, BK=16, bf16 3-term, 3 CTAs/SM. Epilogue emits single fp16.
// ---------------------------------------------------------------------------
__global__ __launch_bounds__(128, 3) void attn_tc(
    const __nv_bfloat16* __restrict__ qkvh,
    const __nv_bfloat16* __restrict__ qkvl,
    const int* __restrict__ pos,
    __half* __restrict__ of)
{
    extern __shared__ __align__(1024) char sm[];
    const uint32_t sb = smem_u32(sm);
    const int tid = threadIdx.x, lane = tid & 31, w = tid >> 5;
    const int qt = gridDim.x - 1 - blockIdx.x;
    const int h = blockIdx.y, g = h >> 2;
    const int q0 = qt * ABQ;
    const float nslope = -exp2f(-0.25f * (float)(h + 1));
    const int qoff = h * HD;
    const int koff = Q_SIZE + g * HD;
    const int voff = Q_SIZE + KV_SIZE + g * HD;
    const int nt = 4 * (qt + 1);

    float* tab = (float*)(sm + A_TAB);
    for (int i = tid; i < 2048; i += 128) tab[i] = sqrtf((float)i);
    if (tid < ABQ) ((int*)(sm + A_PQ))[tid] = pos[q0 + tid];

#pragma unroll
    for (int i = 0; i < 8; i++) {
        int idx = tid + i * 128;
        int row = idx >> 4, ch = idx & 15;
        size_t go = (size_t)(q0 + row) * QKV_W + qoff + ch * 8;
        cpasync16(sb + A_QH + swzA(row, ch), qkvh + go);
        cpasync16(sb + A_QL + swzA(row, ch), qkvl + go);
    }
    asm volatile("cp.async.commit_group;" ::: "memory");
    asm volatile("cp.async.wait_group 0;" ::: "memory");
    __syncthreads();

    const int arow = w * 16 + (lane & 15);
    const int akh = lane >> 4;
    uint32_t qh[8][4];
#pragma unroll
    for (int kk = 0; kk < 8; kk++)
        ldsm4(qh[kk], sb + A_QH + swzA(arow, kk * 2 + akh));

    const int tr = lane >> 2, c2 = (lane & 3) * 2;
    const int pq0 = ((int*)(sm + A_PQ))[w * 16 + tr];
    const int pq1 = ((int*)(sm + A_PQ))[w * 16 + tr + 8];
    const int brow = (lane & 7) + ((lane & 16) >> 1);
    const int bkh = (lane >> 3) & 1;
    const int vrow = lane & 15, vch = lane >> 4;

    float o[16][4];
#pragma unroll
    for (int j = 0; j < 16; j++)
#pragma unroll
        for (int r = 0; r < 4; r++) o[j][r] = 0.f;
    float mr0 = -1e30f, mr1 = -1e30f, lr0 = 0.f, lr1 = 0.f;

    auto issue = [&](int t) {
        const uint32_t st = sb + A_ST + (t & 1) * A_STG;
        const int k0 = t * ABK;
#pragma unroll
        for (int i = 0; i < 2; i++) {
            int idx = tid + i * 128;
            int row = idx >> 4, ch = idx & 15;
            size_t gk = (size_t)(k0 + row) * QKV_W + koff + ch * 8;
            size_t gv = (size_t)(k0 + row) * QKV_W + voff + ch * 8;
            uint32_t so = swzA(row, ch);
            cpasync16(st + A_KH + so, qkvh + gk);
            cpasync16(st + A_KL + so, qkvl + gk);
            cpasync16(st + A_VH + so, qkvh + gv);
            cpasync16(st + A_VL + so, qkvl + gv);
        }
        if (tid < ABK)
            cpasync4(sb + A_PK + (t & 1) * 64 + tid * 4, pos + k0 + tid);
        asm volatile("cp.async.commit_group;" ::: "memory");
    };

    issue(0);
    for (int t = 0; t < nt; t++) {
        if (t + 1 < nt) {
            issue(t + 1);
            asm volatile("cp.async.wait_group 1;" ::: "memory");
        } else {
            asm volatile("cp.async.wait_group 0;" ::: "memory");
        }
        __syncthreads();

        const uint32_t st = sb + A_ST + (t & 1) * A_STG;
        const int* pks = (const int*)(sm + A_PK + (t & 1) * 64);

        float s4[2][4];
#pragma unroll
        for (int ng = 0; ng < 2; ng++)
#pragma unroll
            for (int r = 0; r < 4; r++) s4[ng][r] = 0.f;
#pragma unroll
        for (int kk = 0; kk < 8; kk++) {
            uint32_t kh4[4], kl4[4], ql4[4];
            ldsm4(kh4, st + A_KH + swzA(brow, kk * 2 + bkh));
            mma_bf16(s4[0], qh[kk], &kh4[0]);
            mma_bf16(s4[1], qh[kk], &kh4[2]);
            ldsm4(kl4, st + A_KL + swzA(brow, kk * 2 + bkh));
            mma_bf16(s4[0], qh[kk], &kl4[0]);
            mma_bf16(s4[1], qh[kk], &kl4[2]);
            ldsm4(ql4, sb + A_QL + swzA(arow, kk * 2 + akh));
            mma_bf16(s4[0], ql4, &kh4[0]);
            mma_bf16(s4[1], ql4, &kh4[2]);
        }

        float mx0 = -FLT_MAX, mx1 = -FLT_MAX;
#pragma unroll
        for (int ng = 0; ng < 2; ng++) {
            int pk0 = pks[ng * 8 + c2], pk1 = pks[ng * 8 + c2 + 1];
            int d00 = pq0 - pk0, d01 = pq0 - pk1;
            int d10 = pq1 - pk0, d11 = pq1 - pk1;
            float v00 = fmaf(nslope, tab[d00 < 0 ? 0 : d00], s4[ng][0]);
            float v01 = fmaf(nslope, tab[d01 < 0 ? 0 : d01], s4[ng][1]);
            float v10 = fmaf(nslope, tab[d10 < 0 ? 0 : d10], s4[ng][2]);
            float v11 = fmaf(nslope, tab[d11 < 0 ? 0 : d11], s4[ng][3]);
            s4[ng][0] = (d00 < 0) ? -FLT_MAX : v00;
            s4[ng][1] = (d01 < 0) ? -FLT_MAX : v01;
            s4[ng][2] = (d10 < 0) ? -FLT_MAX : v10;
            s4[ng][3] = (d11 < 0) ? -FLT_MAX : v11;
            mx0 = fmaxf(mx0, fmaxf(s4[ng][0], s4[ng][1]));
            mx1 = fmaxf(mx1, fmaxf(s4[ng][2], s4[ng][3]));
        }
        mx0 = fmaxf(mx0, __shfl_xor_sync(0xffffffffu, mx0, 1));
        mx0 = fmaxf(mx0, __shfl_xor_sync(0xffffffffu, mx0, 2));
        mx1 = fmaxf(mx1, __shfl_xor_sync(0xffffffffu, mx1, 1));
        mx1 = fmaxf(mx1, __shfl_xor_sync(0xffffffffu, mx1, 2));
        float mn0 = fmaxf(mr0, mx0), mn1 = fmaxf(mr1, mx1);
        float fac0 = __expf(mr0 - mn0), fac1 = __expf(mr1 - mn1);
        mr0 = mn0; mr1 = mn1;

        float sum0 = 0.f, sum1 = 0.f;
        uint32_t pa[4], pla[4];
#pragma unroll
        for (int ng = 0; ng < 2; ng++) {
            float p0 = __expf(s4[ng][0] - mn0);
            float p1 = __expf(s4[ng][1] - mn0);
            float p2 = __expf(s4[ng][2] - mn1);
            float p3 = __expf(s4[ng][3] - mn1);
            sum0 += p0 + p1;
            sum1 += p2 + p3;
            uint32_t hp01, lp01, hp23, lp23;
            split2(p0, p1, hp01, lp01);
            split2(p2, p3, hp23, lp23);
            pa[ng * 2]      = hp01;
            pa[ng * 2 + 1]  = hp23;
            pla[ng * 2]     = lp01;
            pla[ng * 2 + 1] = lp23;
        }
        sum0 += __shfl_xor_sync(0xffffffffu, sum0, 1);
        sum0 += __shfl_xor_sync(0xffffffffu, sum0, 2);
        sum1 += __shfl_xor_sync(0xffffffffu, sum1, 1);
        sum1 += __shfl_xor_sync(0xffffffffu, sum1, 2);
        lr0 = lr0 * fac0 + sum0;
        lr1 = lr1 * fac1 + sum1;
#pragma unroll
        for (int j = 0; j < 16; j++) {
            o[j][0] *= fac0; o[j][1] *= fac0;
            o[j][2] *= fac1; o[j][3] *= fac1;
        }

#pragma unroll
        for (int j2 = 0; j2 < 8; j2++) {
            const uint32_t vaddr = swzA(vrow, j2 * 2 + vch);
            uint32_t vh4[4], vl4[4];
            ldsm4t(vh4, st + A_VH + vaddr);
            mma_bf16(o[2 * j2],     pa,  &vh4[0]);
            mma_bf16(o[2 * j2 + 1], pa,  &vh4[2]);
            mma_bf16(o[2 * j2],     pla, &vh4[0]);
            mma_bf16(o[2 * j2 + 1], pla, &vh4[2]);
            ldsm4t(vl4, st + A_VL + vaddr);
            mma_bf16(o[2 * j2],     pa,  &vl4[0]);
            mma_bf16(o[2 * j2 + 1], pa,  &vl4[2]);
        }
        __syncthreads();
    }

    float inv0 = 1.f / lr0, inv1 = 1.f / lr1;
    int row0 = q0 + w * 16 + tr, row1 = row0 + 8;
#pragma unroll
    for (int j = 0; j < 16; j++) {
        int col = qoff + j * 8 + c2;
        *(uint32_t*)(of + (size_t)row0 * Q_SIZE + col) =
            pack_h2(o[j][0] * inv0, o[j][1] * inv0);
        *(uint32_t*)(of + (size_t)row1 * Q_SIZE + col) =
            pack_h2(o[j][2] * inv1, o[j][3] * inv1);
    }
}

// ---------------------------------------------------------------------------
extern "C" void kernel_launch(void* const* d_in, const int* in_sizes, int n_in,
                              void* d_out, int out_size)
{
    (void)in_sizes; (void)n_in; (void)out_size;
    const int*   pos  = (const int*)d_in[0];
    const float* hs   = (const float*)d_in[1];
    const float* wqkv = (const float*)d_in[2];
    const float* wo   = (const float*)d_in[3];
    float* out = (float*)d_out;

    __half *hs_f, *wq_h, *wq_l, *wo_h, *wo_l, *at_f;
    __nv_bfloat16 *qk_h, *qk_l;
    cudaGetSymbolAddress((void**)&hs_f, g_hs_f);
    cudaGetSymbolAddress((void**)&wq_h, g_wqkv_h);
    cudaGetSymbolAddress((void**)&wq_l, g_wqkv_l);
    cudaGetSymbolAddress((void**)&wo_h, g_wo_h);
    cudaGetSymbolAddress((void**)&wo_l, g_wo_l);
    cudaGetSymbolAddress((void**)&qk_h, g_qkv_h);
    cudaGetSymbolAddress((void**)&qk_l, g_qkv_l);
    cudaGetSymbolAddress((void**)&at_f, g_at_f);

    cudaFuncSetAttribute(gemm_h2<0>,
                         cudaFuncAttributeMaxDynamicSharedMemorySize, GEMM_SMEM);
    cudaFuncSetAttribute(gemm_h2<1>,
                         cudaFuncAttributeMaxDynamicSharedMemorySize, GEMM_SMEM);
    cudaFuncSetAttribute(attn_tc,
                         cudaFuncAttributeMaxDynamicSharedMemorySize, A_SMEM);

    // 0) convert/split inputs to fp16
    convh_kernel<<<(S_LEN * HID) / 1024, 256>>>(hs, hs_f, S_LEN * HID);
    splith_kernel<<<(QKV_W * HID) / 1024, 256>>>(wqkv, wq_h, wq_l, QKV_W * HID);
    splith_kernel<<<(HID * HID) / 1024, 256>>>(wo, wo_h, wo_l, HID * HID);

    // 1) QKV projection (fp16 2-term) -> hi/lo bf16, Q pre-scaled
    gemm_h2<1><<<dim3(QKV_W / 128, S_LEN / 128), 256, GEMM_SMEM>>>(
        hs_f, wq_h, wq_l, nullptr, qk_h, qk_l, S_LEN, QKV_W, HID);

    // 2) tensor-core attention (R13 core) -> single fp16
    attn_tc<<<dim3(S_LEN / ABQ, NH), 128, A_SMEM>>>(qk_h, qk_l, pos, at_f);

    // 3) O-projection (fp16 2-term) -> fp32 out
    gemm_h2<0><<<dim3(HID / 128, S_LEN / 128), 256, GEMM_SMEM>>>(
        at_f, wo_h, wo_l, out, nullptr, nullptr, S_LEN, HID, HID);
}

// round 16
// speedup vs baseline: 3.0280x; 1.4836x over previous
#include <cuda_runtime.h>
#include <cuda_bf16.h>
#include <cuda_fp16.h>
#include <math.h>
#include <float.h>
#include <stdint.h>

#define S_LEN  2048
#define HID    4096
#define NH     32
#define HD     128
#define QKV_W  12288
#define Q_SIZE 4096
#define KV_SIZE 1024

// GEMM tile config: CTA 128x128, K chunk 64 (fp16 1-term), 3 stages
#define CHK 64
#define A_OFF  0
#define B_OFF  16384
#define STAGE  32768
#define GEMM_SMEM (3 * STAGE)

// Attention (tensor) config: 128 threads, BQ=64 q rows, BK=16 keys (R13 core)
#define ABQ 64
#define ABK 16
#define A_QH   0
#define A_QL   16384
#define A_ST   32768          // 2 stages x 16KB
#define A_STG  16384
#define A_KH   0
#define A_KL   4096
#define A_VH   8192
#define A_VL   12288
#define A_TAB  65536
#define A_PQ   73728
#define A_PK   73984
#define A_SMEM 74112

// ---------------------------------------------------------------------------
// Scratch (device globals: allocation-free rule)
// ---------------------------------------------------------------------------
__device__ __align__(256) __half g_hs_f[(size_t)S_LEN * HID];
__device__ __align__(256) __half g_wqkv_f[(size_t)QKV_W * HID];
__device__ __align__(256) __half g_wo_f[(size_t)HID * HID];
__device__ __align__(256) __nv_bfloat16 g_qkv_h[(size_t)S_LEN * QKV_W];
__device__ __align__(256) __nv_bfloat16 g_qkv_l[(size_t)S_LEN * QKV_W];
__device__ __align__(256) __half g_at_f[(size_t)S_LEN * Q_SIZE];

// ---------------------------------------------------------------------------
// PTX helpers (plain sm_80-era PTX)
// ---------------------------------------------------------------------------
__device__ __forceinline__ uint32_t smem_u32(const void* p) {
    uint32_t a;
    asm("{ .reg .u64 t; cvta.to.shared.u64 t, %1; cvt.u32.u64 %0, t; }"
        : "=r"(a) : "l"(p));
    return a;
}
__device__ __forceinline__ void cpasync16(uint32_t dst, const void* src) {
    asm volatile("cp.async.cg.shared.global [%0], [%1], 16;"
                 :: "r"(dst), "l"(src) : "memory");
}
__device__ __forceinline__ void cpasync4(uint32_t dst, const void* src) {
    asm volatile("cp.async.ca.shared.global [%0], [%1], 4;"
                 :: "r"(dst), "l"(src) : "memory");
}
__device__ __forceinline__ void ldsm4(uint32_t* r, uint32_t addr) {
    asm volatile("ldmatrix.sync.aligned.m8n8.x4.shared.b16 {%0,%1,%2,%3}, [%4];"
                 : "=r"(r[0]), "=r"(r[1]), "=r"(r[2]), "=r"(r[3]) : "r"(addr));
}
__device__ __forceinline__ void ldsm4t(uint32_t* r, uint32_t addr) {
    asm volatile("ldmatrix.sync.aligned.m8n8.x4.trans.shared.b16 {%0,%1,%2,%3}, [%4];"
                 : "=r"(r[0]), "=r"(r[1]), "=r"(r[2]), "=r"(r[3]) : "r"(addr));
}
__device__ __forceinline__ void mma_bf16(float* d, const uint32_t* a,
                                         const uint32_t* b) {
    asm volatile(
        "mma.sync.aligned.m16n8k16.row.col.f32.bf16.bf16.f32 "
        "{%0,%1,%2,%3}, {%4,%5,%6,%7}, {%8,%9}, {%0,%1,%2,%3};"
        : "+f"(d[0]), "+f"(d[1]), "+f"(d[2]), "+f"(d[3])
        : "r"(a[0]), "r"(a[1]), "r"(a[2]), "r"(a[3]), "r"(b[0]), "r"(b[1]));
}
__device__ __forceinline__ void mma_fp16(float* d, const uint32_t* a,
                                         const uint32_t* b) {
    asm volatile(
        "mma.sync.aligned.m16n8k16.row.col.f32.f16.f16.f32 "
        "{%0,%1,%2,%3}, {%4,%5,%6,%7}, {%8,%9}, {%0,%1,%2,%3};"
        : "+f"(d[0]), "+f"(d[1]), "+f"(d[2]), "+f"(d[3])
        : "r"(a[0]), "r"(a[1]), "r"(a[2]), "r"(a[3]), "r"(b[0]), "r"(b[1]));
}
// swizzle for 128B rows (8 x 16B segs)
__device__ __forceinline__ uint32_t swzB(int row, int seg) {
    return row * 128 + ((seg ^ (row & 7)) << 4);
}
// swizzle for attention tiles (256B rows, 16 x 16B chunks)
__device__ __forceinline__ uint32_t swzA(int row, int chunk) {
    return row * 256 + ((chunk ^ (row & 7)) << 4);
}
// bf16 pair split (QKV epilogue / attention P)
__device__ __forceinline__ void split2(float v0, float v1,
                                       uint32_t& hp, uint32_t& lp) {
    uint32_t u0 = __float_as_uint(v0) & 0xFFFF0000u;
    uint32_t u1 = __float_as_uint(v1) & 0xFFFF0000u;
    hp = (u0 >> 16) | u1;
    float r0 = v0 - __uint_as_float(u0);
    float r1 = v1 - __uint_as_float(u1);
    asm("cvt.rn.bf16x2.f32 %0, %1, %2;" : "=r"(lp) : "f"(r1), "f"(r0));
}
__device__ __forceinline__ uint32_t pack_h2(float v0, float v1) {
    uint32_t p;
    asm("cvt.rn.f16x2.f32 %0, %1, %2;" : "=r"(p) : "f"(v1), "f"(v0));
    return p;
}
// fast exp on FMA/ALU pipes (x <= 0; masked -FLT_MAX -> ~0). rel err ~3e-6.
__device__ __forceinline__ float fexp(float x) {
    float t = fmaxf(x * 1.4426950408889634f, -80.f);
    float r;
    asm("cvt.rni.f32.f32 %0, %1;" : "=f"(r) : "f"(t));
    float f = t - r;
    float p = 1.33335581e-3f;
    p = fmaf(p, f, 9.61812910e-3f);
    p = fmaf(p, f, 5.55041087e-2f);
    p = fmaf(p, f, 2.40226507e-1f);
    p = fmaf(p, f, 6.93147181e-1f);
    p = fmaf(p, f, 1.0f);
    int ir = (int)r;
    return __uint_as_float(__float_as_uint(p) + ((uint32_t)ir << 23));
}

// ---------------------------------------------------------------------------
// fp32 -> fp16 single convert
// ---------------------------------------------------------------------------
__global__ __launch_bounds__(256) void convh_kernel(
    const float* __restrict__ x, __half* __restrict__ f, int n)
{
    int i = (blockIdx.x * 256 + threadIdx.x) * 4;
    if (i >= n) return;
    float4 v = *(const float4*)(x + i);
    *(uint2*)(f + i) = make_uint2(pack_h2(v.x, v.y), pack_h2(v.z, v.w));
}

// ---------------------------------------------------------------------------
// HMMA 1-term fp16 GEMM NT: C = A_fp16 * B_fp16^T, fp32 accumulate.
// CTA 128x128, K chunk 64, 3-stage cp.async, ONE barrier per chunk.
// MODE 0: fp32 out. MODE 1: hi/lo bf16 out, cols < Q_SIZE scaled by 128^-0.5.
// ---------------------------------------------------------------------------
template<int MODE>
__global__ __launch_bounds__(256, 2) void gemm_h1(
    const __half* __restrict__ A, const __half* __restrict__ B,
    float* __restrict__ C, __nv_bfloat16* __restrict__ Ch,
    __nv_bfloat16* __restrict__ Cl, int M, int N, int K)
{
    extern __shared__ __align__(128) char smem_g[];
    const uint32_t sb = smem_u32(smem_g);
    const int tid  = threadIdx.x;
    const int lane = tid & 31, warp = tid >> 5;
    const int wm = warp >> 1, wn = warp & 1;
    const int m0 = blockIdx.y << 7, n0 = blockIdx.x << 7;
    const int NC = K / CHK;

    const int a_row = lane & 15;
    const int a_kh  = lane >> 4;
    const int b_row = (lane & 7) + ((lane & 16) >> 1);
    const int b_kh  = (lane >> 3) & 1;

    float acc[2][8][4];
#pragma unroll
    for (int mt = 0; mt < 2; mt++)
#pragma unroll
        for (int ng = 0; ng < 8; ng++)
#pragma unroll
            for (int r = 0; r < 4; r++) acc[mt][ng][r] = 0.f;

    auto load_chunk = [&](int c, int s) {
        const uint32_t st = sb + s * STAGE;
        const int k0 = c * CHK;
#pragma unroll
        for (int i = 0; i < 4; i++) {
            int idx = tid + i * 256;          // 0..1023: 128 rows x 8 segs
            int row = idx >> 3, seg = idx & 7;
            uint32_t so = swzB(row, seg);
            size_t ga = (size_t)(m0 + row) * K + k0 + seg * 8;
            size_t gb = (size_t)(n0 + row) * K + k0 + seg * 8;
            cpasync16(st + A_OFF + so, A + ga);
            cpasync16(st + B_OFF + so, B + gb);
        }
        asm volatile("cp.async.commit_group;" ::: "memory");
    };

    load_chunk(0, 0);
    load_chunk(1, 1);

    int s = 0, s2 = 2;
    for (int c = 0; c < NC; c++) {
        if (c + 1 < NC)
            asm volatile("cp.async.wait_group 1;" ::: "memory");
        else
            asm volatile("cp.async.wait_group 0;" ::: "memory");
        __syncthreads();

        const uint32_t st = sb + s * STAGE;
#pragma unroll
        for (int kk = 0; kk < 4; kk++) {
            uint32_t ah[2][4], bh[4][4];
#pragma unroll
            for (int mt = 0; mt < 2; mt++) {
                int r = wm * 32 + mt * 16 + a_row;
                ldsm4(ah[mt], st + A_OFF + swzB(r, kk * 2 + a_kh));
            }
#pragma unroll
            for (int g = 0; g < 4; g++) {
                int r = wn * 64 + g * 16 + b_row;
                ldsm4(bh[g], st + B_OFF + swzB(r, kk * 2 + b_kh));
            }
#pragma unroll
            for (int mt = 0; mt < 2; mt++)
#pragma unroll
                for (int ng = 0; ng < 8; ng++)
                    mma_fp16(acc[mt][ng], ah[mt], &bh[ng >> 1][(ng & 1) * 2]);
        }
        // 3-stage: stage written by load(c+2) was last read at compute(c-1),
        // ordered by this iteration's barrier. No second barrier needed.
        if (c + 2 < NC) load_chunk(c + 2, s2);
        s  = (s  == 2) ? 0 : s + 1;
        s2 = (s2 == 2) ? 0 : s2 + 1;
    }

    const int tr = lane >> 2, tc = (lane & 3) * 2;
    const float qsc = 0.08838834764831844f;
#pragma unroll
    for (int mt = 0; mt < 2; mt++) {
        int row = m0 + wm * 32 + mt * 16 + tr;
#pragma unroll
        for (int ng = 0; ng < 8; ng++) {
            int col = n0 + wn * 64 + ng * 8 + tc;
            if (MODE == 0) {
                *(float2*)(C + (size_t)row * N + col) =
                    make_float2(acc[mt][ng][0], acc[mt][ng][1]);
                *(float2*)(C + (size_t)(row + 8) * N + col) =
                    make_float2(acc[mt][ng][2], acc[mt][ng][3]);
            } else {
                float sc = (col < Q_SIZE) ? qsc : 1.f;
                uint32_t hp, lp;
                split2(acc[mt][ng][0] * sc, acc[mt][ng][1] * sc, hp, lp);
                *(uint32_t*)(Ch + (size_t)row * N + col) = hp;
                *(uint32_t*)(Cl + (size_t)row * N + col) = lp;
                split2(acc[mt][ng][2] * sc, acc[mt][ng][3] * sc, hp, lp);
                *(uint32_t*)(Ch + (size_t)(row + 8) * N + col) = hp;
                *(uint32_t*)(Cl + (size_t)(row + 8) * N + col) = lp;
            }
        }
    }
}

// ---------------------------------------------------------------------------
// Tensor-core flash attention (R13/R15 core, bf16 3-term) with fast-poly exp
// replacing MUFU __expf. 128 threads / 4 warps, BQ=64, BK=16, 3 CTAs/SM.
// ---------------------------------------------------------------------------
__global__ __launch_bounds__(128, 3) void attn_tc(
    const __nv_bfloat16* __restrict__ qkvh,
    const __nv_bfloat16* __restrict__ qkvl,
    const int* __restrict__ pos,
    __half* __restrict__ of)
{
    extern __shared__ __align__(1024) char sm[];
    const uint32_t sb = smem_u32(sm);
    const int tid = threadIdx.x, lane = tid & 31, w = tid >> 5;
    const int qt = gridDim.x - 1 - blockIdx.x;
    const int h = blockIdx.y, g = h >> 2;
    const int q0 = qt * ABQ;
    const float nslope = -exp2f(-0.25f * (float)(h + 1));
    const int qoff = h * HD;
    const int koff = Q_SIZE + g * HD;
    const int voff = Q_SIZE + KV_SIZE + g * HD;
    const int nt = 4 * (qt + 1);

    float* tab = (float*)(sm + A_TAB);
    for (int i = tid; i < 2048; i += 128) tab[i] = sqrtf((float)i);
    if (tid < ABQ) ((int*)(sm + A_PQ))[tid] = pos[q0 + tid];

#pragma unroll
    for (int i = 0; i < 8; i++) {
        int idx = tid + i * 128;
        int row = idx >> 4, ch = idx & 15;
        size_t go = (size_t)(q0 + row) * QKV_W + qoff + ch * 8;
        cpasync16(sb + A_QH + swzA(row, ch), qkvh + go);
        cpasync16(sb + A_QL + swzA(row, ch), qkvl + go);
    }
    asm volatile("cp.async.commit_group;" ::: "memory");
    asm volatile("cp.async.wait_group 0;" ::: "memory");
    __syncthreads();

    const int arow = w * 16 + (lane & 15);
    const int akh = lane >> 4;
    uint32_t qh[8][4];
#pragma unroll
    for (int kk = 0; kk < 8; kk++)
        ldsm4(qh[kk], sb + A_QH + swzA(arow, kk * 2 + akh));

    const int tr = lane >> 2, c2 = (lane & 3) * 2;
    const int pq0 = ((int*)(sm + A_PQ))[w * 16 + tr];
    const int pq1 = ((int*)(sm + A_PQ))[w * 16 + tr + 8];
    const int brow = (lane & 7) + ((lane & 16) >> 1);
    const int bkh = (lane >> 3) & 1;
    const int vrow = lane & 15, vch = lane >> 4;

    float o[16][4];
#pragma unroll
    for (int j = 0; j < 16; j++)
#pragma unroll
        for (int r = 0; r < 4; r++) o[j][r] = 0.f;
    float mr0 = -1e30f, mr1 = -1e30f, lr0 = 0.f, lr1 = 0.f;

    auto issue = [&](int t) {
        const uint32_t st = sb + A_ST + (t & 1) * A_STG;
        const int k0 = t * ABK;
#pragma unroll
        for (int i = 0; i < 2; i++) {
            int idx = tid + i * 128;
            int row = idx >> 4, ch = idx & 15;
            size_t gk = (size_t)(k0 + row) * QKV_W + koff + ch * 8;
            size_t gv = (size_t)(k0 + row) * QKV_W + voff + ch * 8;
            uint32_t so = swzA(row, ch);
            cpasync16(st + A_KH + so, qkvh + gk);
            cpasync16(st + A_KL + so, qkvl + gk);
            cpasync16(st + A_VH + so, qkvh + gv);
            cpasync16(st + A_VL + so, qkvl + gv);
        }
        if (tid < ABK)
            cpasync4(sb + A_PK + (t & 1) * 64 + tid * 4, pos + k0 + tid);
        asm volatile("cp.async.commit_group;" ::: "memory");
    };

    issue(0);
    for (int t = 0; t < nt; t++) {
        if (t + 1 < nt) {
            issue(t + 1);
            asm volatile("cp.async.wait_group 1;" ::: "memory");
        } else {
            asm volatile("cp.async.wait_group 0;" ::: "memory");
        }
        __syncthreads();

        const uint32_t st = sb + A_ST + (t & 1) * A_STG;
        const int* pks = (const int*)(sm + A_PK + (t & 1) * 64);

        float s4[2][4];
#pragma unroll
        for (int ng = 0; ng < 2; ng++)
#pragma unroll
            for (int r = 0; r < 4; r++) s4[ng][r] = 0.f;
#pragma unroll
        for (int kk = 0; kk < 8; kk++) {
            uint32_t kh4[4], kl4[4], ql4[4];
            ldsm4(kh4, st + A_KH + swzA(brow, kk * 2 + bkh));
            mma_bf16(s4[0], qh[kk], &kh4[0]);
            mma_bf16(s4[1], qh[kk], &kh4[2]);
            ldsm4(kl4, st + A_KL + swzA(brow, kk * 2 + bkh));
            mma_bf16(s4[0], qh[kk], &kl4[0]);
            mma_bf16(s4[1], qh[kk], &kl4[2]);
            ldsm4(ql4, sb + A_QL + swzA(arow, kk * 2 + akh));
            mma_bf16(s4[0], ql4, &kh4[0]);
            mma_bf16(s4[1], ql4, &kh4[2]);
        }

        float mx0 = -FLT_MAX, mx1 = -FLT_MAX;
#pragma unroll
        for (int ng = 0; ng < 2; ng++) {
            int pk0 = pks[ng * 8 + c2], pk1 = pks[ng * 8 + c2 + 1];
            int d00 = pq0 - pk0, d01 = pq0 - pk1;
            int d10 = pq1 - pk0, d11 = pq1 - pk1;
            float v00 = fmaf(nslope, tab[d00 < 0 ? 0 : d00], s4[ng][0]);
            float v01 = fmaf(nslope, tab[d01 < 0 ? 0 : d01], s4[ng][1]);
            float v10 = fmaf(nslope, tab[d10 < 0 ? 0 : d10], s4[ng][2]);
            float v11 = fmaf(nslope, tab[d11 < 0 ? 0 : d11], s4[ng][3]);
            s4[ng][0] = (d00 < 0) ? -FLT_MAX : v00;
            s4[ng][1] = (d01 < 0) ? -FLT_MAX : v01;
            s4[ng][2] = (d10 < 0) ? -FLT_MAX : v10;
            s4[ng][3] = (d11 < 0) ? -FLT_MAX : v11;
            mx0 = fmaxf(mx0, fmaxf(s4[ng][0], s4[ng][1]));
            mx1 = fmaxf(mx1, fmaxf(s4[ng][2], s4[ng][3]));
        }
        mx0 = fmaxf(mx0, __shfl_xor_sync(0xffffffffu, mx0, 1));
        mx0 = fmaxf(mx0, __shfl_xor_sync(0xffffffffu, mx0, 2));
        mx1 = fmaxf(mx1, __shfl_xor_sync(0xffffffffu, mx1, 1));
        mx1 = fmaxf(mx1, __shfl_xor_sync(0xffffffffu, mx1, 2));
        float mn0 = fmaxf(mr0, mx0), mn1 = fmaxf(mr1, mx1);
        float fac0 = fexp(mr0 - mn0), fac1 = fexp(mr1 - mn1);
        mr0 = mn0; mr1 = mn1;

        float sum0 = 0.f, sum1 = 0.f;
        uint32_t pa[4], pla[4];
#pragma unroll
        for (int ng = 0; ng < 2; ng++) {
            float p0 = fexp(s4[ng][0] - mn0);
            float p1 = fexp(s4[ng][1] - mn0);
            float p2 = fexp(s4[ng][2] - mn1);
            float p3 = fexp(s4[ng][3] - mn1);
            sum0 += p0 + p1;
            sum1 += p2 + p3;
            uint32_t hp01, lp01, hp23, lp23;
            split2(p0, p1, hp01, lp01);
            split2(p2, p3, hp23, lp23);
            pa[ng * 2]      = hp01;
            pa[ng * 2 + 1]  = hp23;
            pla[ng * 2]     = lp01;
            pla[ng * 2 + 1] = lp23;
        }
        sum0 += __shfl_xor_sync(0xffffffffu, sum0, 1);
        sum0 += __shfl_xor_sync(0xffffffffu, sum0, 2);
        sum1 += __shfl_xor_sync(0xffffffffu, sum1, 1);
        sum1 += __shfl_xor_sync(0xffffffffu, sum1, 2);
        lr0 = lr0 * fac0 + sum0;
        lr1 = lr1 * fac1 + sum1;
#pragma unroll
        for (int j = 0; j < 16; j++) {
            o[j][0] *= fac0; o[j][1] *= fac0;
            o[j][2] *= fac1; o[j][3] *= fac1;
        }

#pragma unroll
        for (int j2 = 0; j2 < 8; j2++) {
            const uint32_t vaddr = swzA(vrow, j2 * 2 + vch);
            uint32_t vh4[4], vl4[4];
            ldsm4t(vh4, st + A_VH + vaddr);
            mma_bf16(o[2 * j2],     pa,  &vh4[0]);
            mma_bf16(o[2 * j2 + 1], pa,  &vh4[2]);
            mma_bf16(o[2 * j2],     pla, &vh4[0]);
            mma_bf16(o[2 * j2 + 1], pla, &vh4[2]);
            ldsm4t(vl4, st + A_VL + vaddr);
            mma_bf16(o[2 * j2],     pa,  &vl4[0]);
            mma_bf16(o[2 * j2 + 1], pa,  &vl4[2]);
        }
        __syncthreads();
    }

    float inv0 = 1.f / lr0, inv1 = 1.f / lr1;
    int row0 = q0 + w * 16 + tr, row1 = row0 + 8;
#pragma unroll
    for (int j = 0; j < 16; j++) {
        int col = qoff + j * 8 + c2;
        *(uint32_t*)(of + (size_t)row0 * Q_SIZE + col) =
            pack_h2(o[j][0] * inv0, o[j][1] * inv0);
        *(uint32_t*)(of + (size_t)row1 * Q_SIZE + col) =
            pack_h2(o[j][2] * inv1, o[j][3] * inv1);
    }
}

// ---------------------------------------------------------------------------
extern "C" void kernel_launch(void* const* d_in, const int* in_sizes, int n_in,
                              void* d_out, int out_size)
{
    (void)in_sizes; (void)n_in; (void)out_size;
    const int*   pos  = (const int*)d_in[0];
    const float* hs   = (const float*)d_in[1];
    const float* wqkv = (const float*)d_in[2];
    const float* wo   = (const float*)d_in[3];
    float* out = (float*)d_out;

    __half *hs_f, *wq_f, *wo_f, *at_f;
    __nv_bfloat16 *qk_h, *qk_l;
    cudaGetSymbolAddress((void**)&hs_f, g_hs_f);
    cudaGetSymbolAddress((void**)&wq_f, g_wqkv_f);
    cudaGetSymbolAddress((void**)&wo_f, g_wo_f);
    cudaGetSymbolAddress((void**)&qk_h, g_qkv_h);
    cudaGetSymbolAddress((void**)&qk_l, g_qkv_l);
    cudaGetSymbolAddress((void**)&at_f, g_at_f);

    cudaFuncSetAttribute(gemm_h1<0>,
                         cudaFuncAttributeMaxDynamicSharedMemorySize, GEMM_SMEM);
    cudaFuncSetAttribute(gemm_h1<1>,
                         cudaFuncAttributeMaxDynamicSharedMemorySize, GEMM_SMEM);
    cudaFuncSetAttribute(attn_tc,
                         cudaFuncAttributeMaxDynamicSharedMemorySize, A_SMEM);

    // 0) convert inputs to fp16 (single)
    convh_kernel<<<(S_LEN * HID) / 1024, 256>>>(hs, hs_f, S_LEN * HID);
    convh_kernel<<<(QKV_W * HID) / 1024, 256>>>(wqkv, wq_f, QKV_W * HID);
    convh_kernel<<<(HID * HID) / 1024, 256>>>(wo, wo_f, HID * HID);

    // 1) QKV projection (fp16 1-term) -> hi/lo bf16, Q pre-scaled
    gemm_h1<1><<<dim3(QKV_W / 128, S_LEN / 128), 256, GEMM_SMEM>>>(
        hs_f, wq_f, nullptr, qk_h, qk_l, S_LEN, QKV_W, HID);

    // 2) tensor-core attention (bf16 3-term core, fast exp) -> single fp16
    attn_tc<<<dim3(S_LEN / ABQ, NH), 128, A_SMEM>>>(qk_h, qk_l, pos, at_f);

    // 3) O-projection (fp16 1-term) -> fp32 out
    gemm_h1<0><<<dim3(HID / 128, S_LEN / 128), 256, GEMM_SMEM>>>(
        at_f, wo_f, out, nullptr, nullptr, S_LEN, HID, HID);
}